// round 3
// baseline (speedup 1.0000x reference)
#include <cuda_runtime.h>
#include <cuda_bf16.h>
#include <math.h>

// Problem constants
#define BSZ 32
#define TX  64
#define TY  64
#define DD  512
#define HH  512
#define G4  2048   // 4*H
#define VV  32000

// ---------------- scratch (device globals; no allocation allowed) ----------------
__device__ float g_pre_enc[TX * BSZ * G4];   // [t][b][4H]  x@Wx+b for encoder
__device__ float g_pre_dec[TY * BSZ * G4];   // [t][b][4H]  x@Wx+b for decoder
__device__ float g_hbuf[2][BSZ * HH];        // ping-pong h state
__device__ float g_cbuf[2][BSZ * HH];        // ping-pong c state
__device__ float g_hs[BSZ * TY * HH];        // decoder outputs, (b,t) row order, zeroed past len

// =====================================================================
// Generic fp32 tiled GEMM:  C[M,N] = gather(A)[M,K] @ B[K,N] (+bias)
// If idx != nullptr: row m -> A row idx[(m%32)*idxT + (m/32)]  (embedding gather,
// m ordered (t,b) with b fastest, matching pre-activation layout [t][b][:]).
// BM=BN=128, BK=8, 256 threads, 8x8 microtile, double-buffered smem.
// =====================================================================
__global__ __launch_bounds__(256)
void gemm_f32(const float* __restrict__ A, const int* __restrict__ idx, int idxT,
              const float* __restrict__ Bm, const float* __restrict__ bias,
              float* __restrict__ C, int M, int N, int K)
{
    __shared__ float As[2][8][128];
    __shared__ float Bs[2][8][128];

    const int tid = threadIdx.x;
    const int m0 = blockIdx.y * 128;
    const int n0 = blockIdx.x * 128;

    // A-tile load mapping: 128x8 = 1024 floats / 256 thr = 1 float4 each
    const int a_row = tid >> 1;
    const int a_k   = (tid & 1) * 4;
    const float* a_ptr;
    {
        int m = m0 + a_row;
        int row;
        if (idx) {
            int b = m & 31;
            int t = m >> 5;
            row = idx[b * idxT + t];
        } else {
            row = m;
        }
        a_ptr = A + (size_t)row * K;
    }

    // B-tile load mapping: 8x128 floats, 1 float4 each
    const int b_k = tid >> 5;
    const int b_n = (tid & 31) * 4;
    const float* b_ptr = Bm + (size_t)b_k * N + n0 + b_n;

    const int tm0 = (tid >> 4) * 8;
    const int tn0 = (tid & 15) * 8;

    float acc[8][8];
#pragma unroll
    for (int i = 0; i < 8; i++)
#pragma unroll
        for (int j = 0; j < 8; j++) acc[i][j] = 0.f;

    float4 av = *(const float4*)(a_ptr + a_k);
    float4 bv = *(const float4*)(b_ptr);

    int buf = 0;
    for (int k0 = 0; k0 < K; k0 += 8) {
        As[buf][a_k + 0][a_row] = av.x;
        As[buf][a_k + 1][a_row] = av.y;
        As[buf][a_k + 2][a_row] = av.z;
        As[buf][a_k + 3][a_row] = av.w;
        *(float4*)&Bs[buf][b_k][b_n] = bv;
        __syncthreads();

        if (k0 + 8 < K) {
            av = *(const float4*)(a_ptr + k0 + 8 + a_k);
            bv = *(const float4*)(b_ptr + (size_t)(k0 + 8) * N);
        }

#pragma unroll
        for (int kk = 0; kk < 8; kk++) {
            float ar[8], br[8];
            *(float4*)(ar)     = *(const float4*)&As[buf][kk][tm0];
            *(float4*)(ar + 4) = *(const float4*)&As[buf][kk][tm0 + 4];
            *(float4*)(br)     = *(const float4*)&Bs[buf][kk][tn0];
            *(float4*)(br + 4) = *(const float4*)&Bs[buf][kk][tn0 + 4];
#pragma unroll
            for (int i = 0; i < 8; i++)
#pragma unroll
                for (int j = 0; j < 8; j++) acc[i][j] += ar[i] * br[j];
        }
        buf ^= 1;
        // one sync/iter is safe with double buffering (writes go to the other buf)
    }

#pragma unroll
    for (int i = 0; i < 8; i++) {
        const int m = m0 + tm0 + i;
        float* crow = C + (size_t)m * N + n0 + tn0;
#pragma unroll
        for (int j = 0; j < 8; j += 4) {
            float4 v;
            v.x = acc[i][j + 0]; v.y = acc[i][j + 1];
            v.z = acc[i][j + 2]; v.w = acc[i][j + 3];
            if (bias) {
                const float* bb = bias + n0 + tn0 + j;
                v.x += bb[0]; v.y += bb[1]; v.z += bb[2]; v.w += bb[3];
            }
            *(float4*)(crow + j) = v;
        }
    }
}

// =====================================================================
// One LSTM time step:  z = pre_t + h_in @ Wh ; gates ; masked state update.
// Grid: 128 CTAs x 128 threads. CTA nt owns gate columns n = nt*4 .. nt*4+3
// (and the matching i/j/f/o z-columns, so no cross-CTA dependency).
// thread: lane = b (0..31), warp = local gate column (0..3).
// h_in loaded transposed into padded smem in two 256-k phases.
// =====================================================================
__global__ __launch_bounds__(128)
void lstm_step(const float* __restrict__ pre_t,   // [32][2048] slice for this t
               const float* __restrict__ Wh,      // [512][2048]  (= W + D*4H)
               const float* __restrict__ hin,     // [32][512]
               const float* __restrict__ cin,     // [32][512]
               float* __restrict__ hout,
               float* __restrict__ cout,
               float* __restrict__ hs_out,        // null for encoder; else [b*64+t][512]
               const int* __restrict__ len,
               int t)
{
    __shared__ float hsm[256 * 33];   // padded transpose: hsm[k*33 + b]

    const int tid  = threadIdx.x;
    const int lane = tid & 31;        // b
    const int w    = tid >> 5;        // 0..3
    const int n    = blockIdx.x * 4 + w;   // 0..511

    float acc0 = 0.f, acc1 = 0.f, acc2 = 0.f, acc3 = 0.f;

    for (int p = 0; p < 2; p++) {
        const int kbase = p * 256;
        // coalesced global read, conflict-free padded smem store
        for (int i = tid; i < 32 * 256; i += 128) {
            int b  = i >> 8;
            int kk = i & 255;
            hsm[kk * 33 + b] = hin[b * HH + kbase + kk];
        }
        __syncthreads();

#pragma unroll 8
        for (int kk = 0; kk < 256; kk++) {
            float hv = hsm[kk * 33 + lane];
            const float* wr = Wh + (size_t)(kbase + kk) * G4 + n;
            acc0 += hv * __ldg(wr);
            acc1 += hv * __ldg(wr + 512);
            acc2 += hv * __ldg(wr + 1024);
            acc3 += hv * __ldg(wr + 1536);
        }
        __syncthreads();
    }

    const int b = lane;
    const float* pz = pre_t + b * G4 + n;
    float zi = pz[0]    + acc0;
    float zj = pz[512]  + acc1;
    float zf = pz[1024] + acc2;
    float zo = pz[1536] + acc3;

    float co = cin[b * HH + n];
    float fg = 1.f / (1.f + expf(-(zf + 1.0f)));   // forget bias 1.0
    float ig = 1.f / (1.f + expf(-zi));
    float og = 1.f / (1.f + expf(-zo));
    float cn = co * fg + ig * tanhf(zj);
    float hn = tanhf(cn) * og;

    bool m = (t < len[b]);
    hout[b * HH + n] = m ? hn : hin[b * HH + n];
    cout[b * HH + n] = m ? cn : co;
    if (hs_out)
        hs_out[((size_t)b * TY + t) * HH + n] = m ? hn : 0.f;
}

// =====================================================================
// Host launcher (graph-capturable: only memsetAsync + kernel launches)
// inputs: 0 enc_ids[B,TX] i32, 1 dec_ids[B,TY] i32, 2 len_enc[B] i32,
//         3 len_dec[B] i32, 4 E[V,D], 5 enc_W[D+H,4H], 6 enc_b[4H],
//         7 dec_W[D+H,4H], 8 dec_b[4H], 9 proj_W[H,V]
// output: logits f32 [B,TY,V]
// =====================================================================
extern "C" void kernel_launch(void* const* d_in, const int* in_sizes, int n_in,
                              void* d_out, int out_size)
{
    const int*   enc_ids = (const int*)d_in[0];
    const int*   dec_ids = (const int*)d_in[1];
    const int*   len_enc = (const int*)d_in[2];
    const int*   len_dec = (const int*)d_in[3];
    const float* E       = (const float*)d_in[4];
    const float* enc_W   = (const float*)d_in[5];
    const float* enc_b   = (const float*)d_in[6];
    const float* dec_W   = (const float*)d_in[7];
    const float* dec_b   = (const float*)d_in[8];
    const float* proj_W  = (const float*)d_in[9];
    float*       out     = (float*)d_out;

    float *pre_enc, *pre_dec, *hbuf, *cbuf, *hs;
    cudaGetSymbolAddress((void**)&pre_enc, g_pre_enc);
    cudaGetSymbolAddress((void**)&pre_dec, g_pre_dec);
    cudaGetSymbolAddress((void**)&hbuf,    g_hbuf);
    cudaGetSymbolAddress((void**)&cbuf,    g_cbuf);
    cudaGetSymbolAddress((void**)&hs,      g_hs);

    float* h0 = hbuf;                  // buffer 0
    float* h1 = hbuf + BSZ * HH;       // buffer 1
    float* c0 = cbuf;
    float* c1 = cbuf + BSZ * HH;

    // zero initial state (buffer 0 is the s=0 input)
    cudaMemsetAsync(h0, 0, BSZ * HH * sizeof(float), 0);
    cudaMemsetAsync(c0, 0, BSZ * HH * sizeof(float), 0);

    // Pre-activations: x@Wx + b for all timesteps (embedding gather fused)
    {
        dim3 grid(G4 / 128, (TX * BSZ) / 128);
        gemm_f32<<<grid, 256>>>(E, enc_ids, TX, enc_W, enc_b,
                                pre_enc, TX * BSZ, G4, DD);
        gemm_f32<<<grid, 256>>>(E, dec_ids, TY, dec_W, dec_b,
                                pre_dec, TY * BSZ, G4, DD);
    }

    const float* enc_Wh = enc_W + (size_t)DD * G4;
    const float* dec_Wh = dec_W + (size_t)DD * G4;

    // Encoder recurrence (global step s: in = parity(s), out = parity(s+1))
    for (int s = 0; s < TX; s++) {
        const float* hi = (s & 1) ? h1 : h0;
        const float* ci = (s & 1) ? c1 : c0;
        float* ho = (s & 1) ? h0 : h1;
        float* cc = (s & 1) ? c0 : c1;
        lstm_step<<<128, 128>>>(pre_enc + (size_t)s * BSZ * G4, enc_Wh,
                                hi, ci, ho, cc, nullptr, len_enc, s);
    }
    // Decoder recurrence (continues parity: global step 64+s has parity s)
    for (int s = 0; s < TY; s++) {
        const float* hi = (s & 1) ? h1 : h0;
        const float* ci = (s & 1) ? c1 : c0;
        float* ho = (s & 1) ? h0 : h1;
        float* cc = (s & 1) ? c0 : c1;
        lstm_step<<<128, 128>>>(pre_dec + (size_t)s * BSZ * G4, dec_Wh,
                                hi, ci, ho, cc, hs, len_dec, s);
    }

    // Projection: logits = hs @ proj_W  (hs rows are (b,t)-ordered and already
    // zeroed past length, so the output mask is implicit)
    {
        dim3 grid(VV / 128, (BSZ * TY) / 128);
        gemm_f32<<<grid, 256>>>(hs, nullptr, 0, proj_W, nullptr,
                                out, BSZ * TY, VV, DD);
    }
}

// round 4
// speedup vs baseline: 1.6926x; 1.6926x over previous
#include <cuda_runtime.h>
#include <cuda_bf16.h>
#include <math.h>

// Problem constants
#define BSZ 32
#define TX  64
#define TY  64
#define DD  512
#define HH  512
#define G4  2048   // 4*H
#define VV  32000

#define NCTA 128   // persistent LSTM CTAs (1 per SM, all co-resident)
#define NTHR 256

// ---------------- scratch (device globals; no allocation allowed) ----------------
__device__ float g_pre_enc[TX * BSZ * G4];   // [t][b][4H]
__device__ float g_pre_dec[TY * BSZ * G4];   // [t][b][4H]
__device__ float g_hbuf[2][BSZ * HH];        // ping-pong h state
__device__ float g_hs[BSZ * TY * HH];        // decoder outputs (b,t)-ordered, zeroed past len
__device__ unsigned g_bcount;                // barrier arrival counter
__device__ unsigned g_bgen;                  // barrier generation

// =====================================================================
// Generic fp32 tiled GEMM:  C[M,N] = gather(A)[M,K] @ B[K,N] (+bias)
// (unchanged from passing round; used for pre-activations + projection)
// =====================================================================
__global__ __launch_bounds__(256)
void gemm_f32(const float* __restrict__ A, const int* __restrict__ idx, int idxT,
              const float* __restrict__ Bm, const float* __restrict__ bias,
              float* __restrict__ C, int M, int N, int K)
{
    __shared__ float As[2][8][128];
    __shared__ float Bs[2][8][128];

    const int tid = threadIdx.x;
    const int m0 = blockIdx.y * 128;
    const int n0 = blockIdx.x * 128;

    const int a_row = tid >> 1;
    const int a_k   = (tid & 1) * 4;
    const float* a_ptr;
    {
        int m = m0 + a_row;
        int row;
        if (idx) {
            int b = m & 31;
            int t = m >> 5;
            row = idx[b * idxT + t];
        } else {
            row = m;
        }
        a_ptr = A + (size_t)row * K;
    }

    const int b_k = tid >> 5;
    const int b_n = (tid & 31) * 4;
    const float* b_ptr = Bm + (size_t)b_k * N + n0 + b_n;

    const int tm0 = (tid >> 4) * 8;
    const int tn0 = (tid & 15) * 8;

    float acc[8][8];
#pragma unroll
    for (int i = 0; i < 8; i++)
#pragma unroll
        for (int j = 0; j < 8; j++) acc[i][j] = 0.f;

    float4 av = *(const float4*)(a_ptr + a_k);
    float4 bv = *(const float4*)(b_ptr);

    int buf = 0;
    for (int k0 = 0; k0 < K; k0 += 8) {
        As[buf][a_k + 0][a_row] = av.x;
        As[buf][a_k + 1][a_row] = av.y;
        As[buf][a_k + 2][a_row] = av.z;
        As[buf][a_k + 3][a_row] = av.w;
        *(float4*)&Bs[buf][b_k][b_n] = bv;
        __syncthreads();

        if (k0 + 8 < K) {
            av = *(const float4*)(a_ptr + k0 + 8 + a_k);
            bv = *(const float4*)(b_ptr + (size_t)(k0 + 8) * N);
        }

#pragma unroll
        for (int kk = 0; kk < 8; kk++) {
            float ar[8], br[8];
            *(float4*)(ar)     = *(const float4*)&As[buf][kk][tm0];
            *(float4*)(ar + 4) = *(const float4*)&As[buf][kk][tm0 + 4];
            *(float4*)(br)     = *(const float4*)&Bs[buf][kk][tn0];
            *(float4*)(br + 4) = *(const float4*)&Bs[buf][kk][tn0 + 4];
#pragma unroll
            for (int i = 0; i < 8; i++)
#pragma unroll
                for (int j = 0; j < 8; j++) acc[i][j] += ar[i] * br[j];
        }
        buf ^= 1;
    }

#pragma unroll
    for (int i = 0; i < 8; i++) {
        const int m = m0 + tm0 + i;
        float* crow = C + (size_t)m * N + n0 + tn0;
#pragma unroll
        for (int j = 0; j < 8; j += 4) {
            float4 v;
            v.x = acc[i][j + 0]; v.y = acc[i][j + 1];
            v.z = acc[i][j + 2]; v.w = acc[i][j + 3];
            if (bias) {
                const float* bb = bias + n0 + tn0 + j;
                v.x += bb[0]; v.y += bb[1]; v.z += bb[2]; v.w += bb[3];
            }
            *(float4*)(crow + j) = v;
        }
    }
}

// =====================================================================
// Software grid barrier (sense-reversing via generation counter).
// Valid because all NCTA CTAs are co-resident (1 per SM).
// Release: threadfence before arrival. Acquire: threadfence after spin
// (emits CCTL.IVALL -> invalidates this SM's L1).
// =====================================================================
__device__ __forceinline__ void grid_barrier()
{
    __syncthreads();
    if (threadIdx.x == 0) {
        unsigned gen = *(volatile unsigned*)&g_bgen;
        __threadfence();
        unsigned t = atomicAdd(&g_bcount, 1);
        if (t == NCTA - 1) {
            atomicExch(&g_bcount, 0);
            __threadfence();
            atomicAdd(&g_bgen, 1);
        } else {
            while (*(volatile unsigned*)&g_bgen == gen) { }
        }
        __threadfence();
    }
    __syncthreads();
}

// =====================================================================
// Persistent LSTM: runs ALL 128 timesteps (64 enc + 64 dec) in one launch.
// CTA c owns h-columns [4c, 4c+4)  (=> z-columns g*512 + 4c + hc, g=0..3).
// Its Wh slice (512 x 16 fp32 = 32KB) lives in smem for the whole phase.
// c-state lives in registers of threads 0..127 (thread = (b, hc)).
// h ping-pongs through global memory with a grid barrier per step.
//
// smem layout (dynamic, ~99KB):
//   whs [16][520]  : Wh slice, transposed to [zcol][k]   (zcol = g*4+hc)
//   hsm [32][516]  : current h, [b][k]
//   zbuf[32][17]   : gate pre-activations for the exchange phase
// =====================================================================
__global__ __launch_bounds__(NTHR, 1)
void lstm_persist(const float* __restrict__ pre_enc, const float* __restrict__ pre_dec,
                  const float* __restrict__ enc_Wh, const float* __restrict__ dec_Wh,
                  const int* __restrict__ len_enc, const int* __restrict__ len_dec,
                  float* __restrict__ hbuf, float* __restrict__ hs)
{
    extern __shared__ float sm[];
    float* whs  = sm;                    // 16*520 = 8320 floats
    float* hsm  = sm + 16 * 520;         // 32*516 = 16512 floats
    float* zbuf = hsm + 32 * 516;        // 32*17  = 544 floats

    const int tid = threadIdx.x;
    const int cta = blockIdx.x;
    const int zc  = tid & 15;            // z-column within slice (g*4+hc)
    const int bb  = tid >> 4;            // 0..15
    const int b0  = bb * 2, b1 = bb * 2 + 1;

    float c_reg = 0.f;                   // cell state for (b = tid>>2, hc = tid&3), tid<128

    for (int phase = 0; phase < 2; phase++) {
        const float* Wh  = phase ? dec_Wh  : enc_Wh;
        const float* pre = phase ? pre_dec : pre_enc;
        const int*   len = phase ? len_dec : len_enc;

        // Load Wh slice (transposed) into smem — once per phase.
        for (int i = tid; i < 16 * 512; i += NTHR) {
            int z = i >> 9, k = i & 511;
            whs[z * 520 + k] =
                __ldg(&Wh[(size_t)k * G4 + (z >> 2) * 512 + cta * 4 + (z & 3)]);
        }
        __syncthreads();

        for (int s = 0; s < 64; s++) {
            const int sigma = phase * 64 + s;
            const float* hin  = hbuf + (sigma & 1) * (BSZ * HH);
            float*       hout = hbuf + ((sigma + 1) & 1) * (BSZ * HH);

            // Stage h into smem (L2-coherent loads; L1 may be stale across SMs).
            for (int i = tid; i < (BSZ * HH) / 4; i += NTHR) {
                int b = i >> 7, k4 = i & 127;
                float4 v = __ldcg((const float4*)&hin[b * HH + k4 * 4]);
                *(float4*)&hsm[b * 516 + k4 * 4] = v;
            }
            __syncthreads();

            // z[b][zc] = sum_k h[b][k] * whs[zc][k]   (2 b-rows per thread)
            float acc0 = 0.f, acc1 = 0.f;
            const float* wr  = &whs[zc * 520];
            const float* h0r = &hsm[b0 * 516];
            const float* h1r = &hsm[b1 * 516];
#pragma unroll 4
            for (int k = 0; k < 512; k += 4) {
                float4 w4 = *(const float4*)&wr[k];
                float4 ha = *(const float4*)&h0r[k];
                float4 hb = *(const float4*)&h1r[k];
                acc0 += ha.x * w4.x + ha.y * w4.y + ha.z * w4.z + ha.w * w4.w;
                acc1 += hb.x * w4.x + hb.y * w4.y + hb.z * w4.z + hb.w * w4.w;
            }
            zbuf[b0 * 17 + zc] = acc0;
            zbuf[b1 * 17 + zc] = acc1;
            __syncthreads();

            // Gate fusion + state update (threads 0..127: one (b, hc) each)
            if (tid < 128) {
                const int b  = tid >> 2;
                const int hc = tid & 3;
                const int n  = cta * 4 + hc;
                const float* pz = pre + (size_t)s * BSZ * G4 + (size_t)b * G4 + n;

                float zi = pz[0]    + zbuf[b * 17 + hc];
                float zj = pz[512]  + zbuf[b * 17 + 4 + hc];
                float zf = pz[1024] + zbuf[b * 17 + 8 + hc];
                float zo = pz[1536] + zbuf[b * 17 + 12 + hc];

                float fg = 1.f / (1.f + expf(-(zf + 1.0f)));   // forget bias 1.0
                float ig = 1.f / (1.f + expf(-zi));
                float og = 1.f / (1.f + expf(-zo));
                float cn = c_reg * fg + ig * tanhf(zj);
                float hn = tanhf(cn) * og;

                bool m = (s < len[b]);
                float hprev = hsm[b * 516 + n];
                c_reg = m ? cn : c_reg;
                hout[b * HH + n] = m ? hn : hprev;
                if (phase)
                    hs[((size_t)b * TY + s) * HH + n] = m ? hn : 0.f;
            }

            grid_barrier();   // publish h, everyone advances together
        }
    }
}

// =====================================================================
// Host launcher (graph-capturable)
// inputs: 0 enc_ids[B,TX] i32, 1 dec_ids[B,TY] i32, 2 len_enc[B] i32,
//         3 len_dec[B] i32, 4 E[V,D], 5 enc_W[D+H,4H], 6 enc_b[4H],
//         7 dec_W[D+H,4H], 8 dec_b[4H], 9 proj_W[H,V]
// output: logits f32 [B,TY,V]
// =====================================================================
extern "C" void kernel_launch(void* const* d_in, const int* in_sizes, int n_in,
                              void* d_out, int out_size)
{
    const int*   enc_ids = (const int*)d_in[0];
    const int*   dec_ids = (const int*)d_in[1];
    const int*   len_enc = (const int*)d_in[2];
    const int*   len_dec = (const int*)d_in[3];
    const float* E       = (const float*)d_in[4];
    const float* enc_W   = (const float*)d_in[5];
    const float* enc_b   = (const float*)d_in[6];
    const float* dec_W   = (const float*)d_in[7];
    const float* dec_b   = (const float*)d_in[8];
    const float* proj_W  = (const float*)d_in[9];
    float*       out     = (float*)d_out;

    float *pre_enc, *pre_dec, *hbuf, *hs;
    cudaGetSymbolAddress((void**)&pre_enc, g_pre_enc);
    cudaGetSymbolAddress((void**)&pre_dec, g_pre_dec);
    cudaGetSymbolAddress((void**)&hbuf,    g_hbuf);
    cudaGetSymbolAddress((void**)&hs,      g_hs);

    const size_t smem_bytes = (16 * 520 + 32 * 516 + 32 * 17) * sizeof(float);
    static bool attr_set = false;
    if (!attr_set) {
        cudaFuncSetAttribute(lstm_persist,
                             cudaFuncAttributeMaxDynamicSharedMemorySize,
                             (int)smem_bytes);
        attr_set = true;
    }

    // zero initial h (buffer 0 is the sigma=0 input)
    cudaMemsetAsync(hbuf, 0, BSZ * HH * sizeof(float), 0);

    // Pre-activations: x@Wx + b for all timesteps (embedding gather fused)
    {
        dim3 grid(G4 / 128, (TX * BSZ) / 128);
        gemm_f32<<<grid, 256>>>(E, enc_ids, TX, enc_W, enc_b,
                                pre_enc, TX * BSZ, G4, DD);
        gemm_f32<<<grid, 256>>>(E, dec_ids, TY, dec_W, dec_b,
                                pre_dec, TY * BSZ, G4, DD);
    }

    // Full recurrence (encoder + decoder) in ONE persistent kernel.
    lstm_persist<<<NCTA, NTHR, smem_bytes>>>(
        pre_enc, pre_dec,
        enc_W + (size_t)DD * G4, dec_W + (size_t)DD * G4,
        len_enc, len_dec, hbuf, hs);

    // Projection: logits = hs @ proj_W  (hs rows (b,t)-ordered, pre-masked)
    {
        dim3 grid(VV / 128, (BSZ * TY) / 128);
        gemm_f32<<<grid, 256>>>(hs, nullptr, 0, proj_W, nullptr,
                                out, BSZ * TY, VV, DD);
    }
}

// round 6
// speedup vs baseline: 2.4449x; 1.4444x over previous
#include <cuda_runtime.h>
#include <cuda_bf16.h>
#include <math.h>
#include <stdint.h>

// Problem constants
#define BSZ 32
#define TX  64
#define TY  64
#define DD  512
#define HH  512
#define G4  2048   // 4*H
#define VV  32000

#define NCTA 128   // persistent LSTM CTAs
#define NTHR 256

// ---------------- scratch (device globals; no allocation allowed) ----------------
__device__ float g_pre_enc[TX * BSZ * G4];
__device__ float g_pre_dec[TY * BSZ * G4];
__device__ float g_hbuf[2][BSZ * HH];
__device__ float g_hs[BSZ * TY * HH];
__device__ unsigned g_bcount;
__device__ unsigned g_bgen;

// split-bf16 operands (K-major, K=512 columns)
__device__ __nv_bfloat16 g_Bt_hi[VV * DD],  g_Bt_lo[VV * DD];    // proj_W^T  [V][D]
__device__ __nv_bfloat16 g_WeT_hi[G4 * DD], g_WeT_lo[G4 * DD];   // enc Wx^T  [4H][D]
__device__ __nv_bfloat16 g_WdT_hi[G4 * DD], g_WdT_lo[G4 * DD];   // dec Wx^T  [4H][D]
__device__ __nv_bfloat16 g_Ae_hi[TX * BSZ * DD], g_Ae_lo[TX * BSZ * DD];
__device__ __nv_bfloat16 g_Ad_hi[TY * BSZ * DD], g_Ad_lo[TY * BSZ * DD];
__device__ __nv_bfloat16 g_Ah_hi[BSZ * TY * DD], g_Ah_lo[BSZ * TY * DD];

// ======================= helpers =======================
__device__ __forceinline__ uint32_t smem_u32(const void* p) {
    uint32_t a;
    asm("{ .reg .u64 t; cvta.to.shared.u64 t, %1; cvt.u32.u64 %0, t; }" : "=r"(a) : "l"(p));
    return a;
}

#define LDSM4(r, addr) \
    asm volatile("ldmatrix.sync.aligned.m8n8.x4.shared.b16 {%0,%1,%2,%3}, [%4];" \
        : "=r"((r)[0]), "=r"((r)[1]), "=r"((r)[2]), "=r"((r)[3]) : "r"(addr))

#define MMA16816(d, a, b0, b1) \
    asm volatile("mma.sync.aligned.m16n8k16.row.col.f32.bf16.bf16.f32 " \
        "{%0,%1,%2,%3}, {%4,%5,%6,%7}, {%8,%9}, {%0,%1,%2,%3};" \
        : "+f"((d)[0]), "+f"((d)[1]), "+f"((d)[2]), "+f"((d)[3]) \
        : "r"((a)[0]), "r"((a)[1]), "r"((a)[2]), "r"((a)[3]), "r"(b0), "r"(b1))

#define CP_ASYNC16(dst, src) \
    asm volatile("cp.async.cg.shared.global [%0], [%1], 16;" :: "r"(dst), "l"(src))
#define CP_COMMIT()  asm volatile("cp.async.commit_group;" ::: "memory")
#define CP_WAIT(n)   asm volatile("cp.async.wait_group %0;" :: "n"(n) : "memory")

// =====================================================================
// Split-bf16 tensor-core GEMM via mma.sync (HMMA):
//   C[M,N] = (Ahi+Alo)[M,512] @ (Bhi+Blo)[N,512]^T  (+bias)
// Drops the lo*lo term (~2^-16 relative).
// CTA: 128x128 tile, BK=64 bf16, cp.async double-buffered smem
// (2 x 4 tiles x 16KB = 128KB). 8 warps = 4(M) x 2(N), warp tile 32x64.
// smem rows: 128B (64 bf16) with 16B-unit XOR swizzle (u ^= r&7):
// conflict-free ldmatrix. grid = (M/128, N/128); consecutive blockIdx.x
// share the B tile (L2 reuse for the 32000-wide projection).
// =====================================================================
__global__ __launch_bounds__(256, 1)
void mma_gemm(const __nv_bfloat16* __restrict__ Ahi, const __nv_bfloat16* __restrict__ Alo,
              const __nv_bfloat16* __restrict__ Bhi, const __nv_bfloat16* __restrict__ Blo,
              const float* __restrict__ bias, float* __restrict__ C, int N)
{
    extern __shared__ char smc[];
    const uint32_t sbase = smem_u32(smc);

    const int tid  = threadIdx.x;
    const int wid  = tid >> 5;
    const int lane = tid & 31;
    const int m0 = blockIdx.x * 128;
    const int n0 = blockIdx.y * 128;
    const int wm = (wid & 3) * 32;    // warp M offset in tile
    const int wn = (wid >> 2) * 64;   // warp N offset in tile

    const __nv_bfloat16* srcs[4] = { Ahi, Alo, Bhi, Blo };
    const int rb[4] = { m0, m0, n0, n0 };

    // per-thread load slots: unit index i = tid + q*256 ; r = i>>3, u = i&7
    // dst = buf + t4*16384 + r*128 + ((u ^ (r&7))<<4)
    uint32_t dsts[4];
    const __nv_bfloat16* gsrc[4][4];
    {
#pragma unroll
        for (int q = 0; q < 4; q++) {
            const int i = tid + q * 256;
            const int r = i >> 3, u = i & 7;
            dsts[q] = (uint32_t)(r * 128 + ((u ^ (r & 7)) << 4));
#pragma unroll
            for (int t4 = 0; t4 < 4; t4++)
                gsrc[t4][q] = srcs[t4] + (size_t)(rb[t4] + r) * DD + u * 8;
        }
    }

    float acc[2][8][4];
#pragma unroll
    for (int mt = 0; mt < 2; mt++)
#pragma unroll
        for (int nt = 0; nt < 8; nt++)
#pragma unroll
            for (int e = 0; e < 4; e++) acc[mt][nt][e] = 0.f;

    // ---- prefetch iter 0 ----
#pragma unroll
    for (int t4 = 0; t4 < 4; t4++)
#pragma unroll
        for (int q = 0; q < 4; q++)
            CP_ASYNC16(sbase + t4 * 16384 + dsts[q], gsrc[t4][q]);
    CP_COMMIT();

    // lane-constant fragment address components
    const int lrow15 = lane & 15;
    const int lhalf  = lane >> 4;

    for (int it = 0; it < 8; it++) {
        if (it < 7) {
            const int koff = (it + 1) * 64;   // bf16 elements
            const uint32_t bufn = ((it + 1) & 1) * 65536;
#pragma unroll
            for (int t4 = 0; t4 < 4; t4++)
#pragma unroll
                for (int q = 0; q < 4; q++)
                    CP_ASYNC16(sbase + bufn + t4 * 16384 + dsts[q], gsrc[t4][q] + koff);
            CP_COMMIT();
            CP_WAIT(1);
        } else {
            CP_WAIT(0);
        }
        __syncthreads();

        const uint32_t B = sbase + (it & 1) * 65536;

#pragma unroll
        for (int j = 0; j < 4; j++) {   // k16 step within BK=64
            uint32_t ah[2][4], al[2][4];
            uint32_t bh[4][4], bl[4][4];
#pragma unroll
            for (int mt = 0; mt < 2; mt++) {
                const int row = wm + mt * 16 + lrow15;
                const int unit = j * 2 + lhalf;
                const uint32_t addr = B + row * 128 + (((unit ^ (row & 7))) << 4);
                LDSM4(ah[mt], addr);
                LDSM4(al[mt], addr + 16384);
            }
#pragma unroll
            for (int g = 0; g < 4; g++) {
                const int row = wn + g * 16 + lrow15;
                const int unit = j * 2 + lhalf;
                const uint32_t addr = B + 32768 + row * 128 + (((unit ^ (row & 7))) << 4);
                LDSM4(bh[g], addr);
                LDSM4(bl[g], addr + 16384);
            }
#pragma unroll
            for (int mt = 0; mt < 2; mt++)
#pragma unroll
                for (int nt = 0; nt < 8; nt++) {
                    const int g = nt >> 1, o = nt & 1;
                    MMA16816(acc[mt][nt], ah[mt], bh[g][o], bh[g][o + 2]); // hi*hi
                    MMA16816(acc[mt][nt], ah[mt], bl[g][o], bl[g][o + 2]); // hi*lo
                    MMA16816(acc[mt][nt], al[mt], bh[g][o], bh[g][o + 2]); // lo*hi
                }
        }
        __syncthreads();
    }

    // ---- epilogue ----
    const int er = m0 + wm + (lane >> 2);
    const int ec = n0 + wn + (lane & 3) * 2;
#pragma unroll
    for (int mt = 0; mt < 2; mt++) {
#pragma unroll
        for (int nt = 0; nt < 8; nt++) {
            const int row = er + mt * 16;
            const int col = ec + nt * 8;
            float b0 = 0.f, b1 = 0.f;
            if (bias) { b0 = bias[col]; b1 = bias[col + 1]; }
            float* p0 = C + (size_t)row * N + col;
            float* p1 = C + (size_t)(row + 8) * N + col;
            p0[0] = acc[mt][nt][0] + b0;
            p0[1] = acc[mt][nt][1] + b1;
            p1[0] = acc[mt][nt][2] + b0;
            p1[1] = acc[mt][nt][3] + b1;
        }
    }
}

// =====================================================================
// Transpose + split:  src[K=512][N] f32  ->  hi/lo [N][512] bf16
// =====================================================================
__global__ void transpose_split(const float* __restrict__ src, int N,
                                __nv_bfloat16* __restrict__ hi, __nv_bfloat16* __restrict__ lo)
{
    __shared__ float t[32][33];
    const int tx = threadIdx.x & 31, ty = threadIdx.x >> 5;
    const int n = blockIdx.x * 32 + tx;
    const int kb = blockIdx.y * 32;
#pragma unroll
    for (int r = 0; r < 32; r += 8)
        t[ty + r][tx] = src[(size_t)(kb + ty + r) * N + n];
    __syncthreads();
#pragma unroll
    for (int r = 0; r < 32; r += 8) {
        const int nn = blockIdx.x * 32 + ty + r;
        const int kk = kb + tx;
        const float v = t[tx][ty + r];
        const __nv_bfloat16 h = __float2bfloat16(v);
        hi[(size_t)nn * DD + kk] = h;
        lo[(size_t)nn * DD + kk] = __float2bfloat16(v - __bfloat162float(h));
    }
}

// Embedding gather + split: row m (b=m&31, t=m>>5) <- E[ids[b*idxT+t]]
__global__ void gather_split(const float* __restrict__ E, const int* __restrict__ ids, int idxT,
                             __nv_bfloat16* __restrict__ hi, __nv_bfloat16* __restrict__ lo)
{
    const int i = blockIdx.x * 256 + threadIdx.x;
    const int row = i >> 9, k = i & 511;
    const int b = row & 31, t = row >> 5;
    const float v = E[(size_t)ids[b * idxT + t] * DD + k];
    const __nv_bfloat16 h = __float2bfloat16(v);
    hi[i] = h;
    lo[i] = __float2bfloat16(v - __bfloat162float(h));
}

// Elementwise split of hs
__global__ void split_convert(const float* __restrict__ src,
                              __nv_bfloat16* __restrict__ hi, __nv_bfloat16* __restrict__ lo)
{
    const int i = blockIdx.x * 256 + threadIdx.x;
    const float v = src[i];
    const __nv_bfloat16 h = __float2bfloat16(v);
    hi[i] = h;
    lo[i] = __float2bfloat16(v - __bfloat162float(h));
}

// =====================================================================
// Software grid barrier (all NCTA CTAs co-resident)
// =====================================================================
__device__ __forceinline__ void grid_barrier()
{
    __syncthreads();
    if (threadIdx.x == 0) {
        unsigned gen = *(volatile unsigned*)&g_bgen;
        __threadfence();
        unsigned t = atomicAdd(&g_bcount, 1);
        if (t == NCTA - 1) {
            atomicExch(&g_bcount, 0);
            __threadfence();
            atomicAdd(&g_bgen, 1);
        } else {
            while (*(volatile unsigned*)&g_bgen == gen) { }
        }
        __threadfence();
    }
    __syncthreads();
}

// =====================================================================
// Persistent LSTM (proven in R4): all 128 timesteps, one launch.
// =====================================================================
__global__ __launch_bounds__(NTHR, 1)
void lstm_persist(const float* __restrict__ pre_enc, const float* __restrict__ pre_dec,
                  const float* __restrict__ enc_Wh, const float* __restrict__ dec_Wh,
                  const int* __restrict__ len_enc, const int* __restrict__ len_dec,
                  float* __restrict__ hbuf, float* __restrict__ hs)
{
    extern __shared__ float smf[];
    float* whs  = smf;                    // 16*520
    float* hsm  = smf + 16 * 520;         // 32*516
    float* zbuf = hsm + 32 * 516;         // 32*17

    const int tid = threadIdx.x;
    const int cta = blockIdx.x;
    const int zc  = tid & 15;
    const int bb  = tid >> 4;
    const int b0  = bb * 2, b1 = bb * 2 + 1;

    float c_reg = 0.f;

    for (int phase = 0; phase < 2; phase++) {
        const float* Wh  = phase ? dec_Wh  : enc_Wh;
        const float* pre = phase ? pre_dec : pre_enc;
        const int*   len = phase ? len_dec : len_enc;

        for (int i = tid; i < 16 * 512; i += NTHR) {
            int z = i >> 9, k = i & 511;
            whs[z * 520 + k] =
                __ldg(&Wh[(size_t)k * G4 + (z >> 2) * 512 + cta * 4 + (z & 3)]);
        }
        __syncthreads();

        for (int s = 0; s < 64; s++) {
            const int sigma = phase * 64 + s;
            const float* hin  = hbuf + (sigma & 1) * (BSZ * HH);
            float*       hout = hbuf + ((sigma + 1) & 1) * (BSZ * HH);

            for (int i = tid; i < (BSZ * HH) / 4; i += NTHR) {
                int b = i >> 7, k4 = i & 127;
                float4 v = __ldcg((const float4*)&hin[b * HH + k4 * 4]);
                *(float4*)&hsm[b * 516 + k4 * 4] = v;
            }
            __syncthreads();

            float acc0 = 0.f, acc1 = 0.f;
            const float* wr  = &whs[zc * 520];
            const float* h0r = &hsm[b0 * 516];
            const float* h1r = &hsm[b1 * 516];
#pragma unroll 4
            for (int k = 0; k < 512; k += 4) {
                float4 w4 = *(const float4*)&wr[k];
                float4 ha = *(const float4*)&h0r[k];
                float4 hb = *(const float4*)&h1r[k];
                acc0 += ha.x * w4.x + ha.y * w4.y + ha.z * w4.z + ha.w * w4.w;
                acc1 += hb.x * w4.x + hb.y * w4.y + hb.z * w4.z + hb.w * w4.w;
            }
            zbuf[b0 * 17 + zc] = acc0;
            zbuf[b1 * 17 + zc] = acc1;
            __syncthreads();

            if (tid < 128) {
                const int b  = tid >> 2;
                const int hc = tid & 3;
                const int n  = cta * 4 + hc;
                const float* pz = pre + (size_t)s * BSZ * G4 + (size_t)b * G4 + n;

                float zi = pz[0]    + zbuf[b * 17 + hc];
                float zj = pz[512]  + zbuf[b * 17 + 4 + hc];
                float zf = pz[1024] + zbuf[b * 17 + 8 + hc];
                float zo = pz[1536] + zbuf[b * 17 + 12 + hc];

                float fg = 1.f / (1.f + expf(-(zf + 1.0f)));
                float ig = 1.f / (1.f + expf(-zi));
                float og = 1.f / (1.f + expf(-zo));
                float cn = c_reg * fg + ig * tanhf(zj);
                float hn = tanhf(cn) * og;

                bool m = (s < len[b]);
                float hprev = hsm[b * 516 + n];
                c_reg = m ? cn : c_reg;
                hout[b * HH + n] = m ? hn : hprev;
                if (phase)
                    hs[((size_t)b * TY + s) * HH + n] = m ? hn : 0.f;
            }
            grid_barrier();
        }
    }
}

// =====================================================================
// Host launcher (graph-capturable)
// =====================================================================
extern "C" void kernel_launch(void* const* d_in, const int* in_sizes, int n_in,
                              void* d_out, int out_size)
{
    const int*   enc_ids = (const int*)d_in[0];
    const int*   dec_ids = (const int*)d_in[1];
    const int*   len_enc = (const int*)d_in[2];
    const int*   len_dec = (const int*)d_in[3];
    const float* E       = (const float*)d_in[4];
    const float* enc_W   = (const float*)d_in[5];
    const float* enc_b   = (const float*)d_in[6];
    const float* dec_W   = (const float*)d_in[7];
    const float* dec_b   = (const float*)d_in[8];
    const float* proj_W  = (const float*)d_in[9];
    float*       out     = (float*)d_out;

    float *pre_enc, *pre_dec, *hbuf, *hs;
    cudaGetSymbolAddress((void**)&pre_enc, g_pre_enc);
    cudaGetSymbolAddress((void**)&pre_dec, g_pre_dec);
    cudaGetSymbolAddress((void**)&hbuf,    g_hbuf);
    cudaGetSymbolAddress((void**)&hs,      g_hs);

    __nv_bfloat16 *Bt_hi, *Bt_lo, *WeT_hi, *WeT_lo, *WdT_hi, *WdT_lo;
    __nv_bfloat16 *Ae_hi, *Ae_lo, *Ad_hi, *Ad_lo, *Ah_hi, *Ah_lo;
    cudaGetSymbolAddress((void**)&Bt_hi,  g_Bt_hi);
    cudaGetSymbolAddress((void**)&Bt_lo,  g_Bt_lo);
    cudaGetSymbolAddress((void**)&WeT_hi, g_WeT_hi);
    cudaGetSymbolAddress((void**)&WeT_lo, g_WeT_lo);
    cudaGetSymbolAddress((void**)&WdT_hi, g_WdT_hi);
    cudaGetSymbolAddress((void**)&WdT_lo, g_WdT_lo);
    cudaGetSymbolAddress((void**)&Ae_hi,  g_Ae_hi);
    cudaGetSymbolAddress((void**)&Ae_lo,  g_Ae_lo);
    cudaGetSymbolAddress((void**)&Ad_hi,  g_Ad_hi);
    cudaGetSymbolAddress((void**)&Ad_lo,  g_Ad_lo);
    cudaGetSymbolAddress((void**)&Ah_hi,  g_Ah_hi);
    cudaGetSymbolAddress((void**)&Ah_lo,  g_Ah_lo);

    const size_t lstm_smem = (16 * 520 + 32 * 516 + 32 * 17) * sizeof(float);
    const size_t gemm_smem = 2 * 4 * 16384;   // 128KB double-buffered tiles
    static bool attr_set = false;
    if (!attr_set) {
        cudaFuncSetAttribute(lstm_persist,
                             cudaFuncAttributeMaxDynamicSharedMemorySize, (int)lstm_smem);
        cudaFuncSetAttribute(mma_gemm,
                             cudaFuncAttributeMaxDynamicSharedMemorySize, (int)gemm_smem);
        attr_set = true;
    }

    cudaMemsetAsync(hbuf, 0, BSZ * HH * sizeof(float), 0);

    // Weight transposes + splits
    transpose_split<<<dim3(VV / 32, DD / 32), 256>>>(proj_W, VV, Bt_hi, Bt_lo);
    transpose_split<<<dim3(G4 / 32, DD / 32), 256>>>(enc_W, G4, WeT_hi, WeT_lo);
    transpose_split<<<dim3(G4 / 32, DD / 32), 256>>>(dec_W, G4, WdT_hi, WdT_lo);

    // Embedding gathers + splits
    gather_split<<<(TX * BSZ * DD) / 256, 256>>>(E, enc_ids, TX, Ae_hi, Ae_lo);
    gather_split<<<(TY * BSZ * DD) / 256, 256>>>(E, dec_ids, TY, Ad_hi, Ad_lo);

    // Pre-activations on tensor cores: pre = emb @ Wx + b   [2048 x 2048]
    mma_gemm<<<dim3(16, G4 / 128), 256, gemm_smem>>>(Ae_hi, Ae_lo, WeT_hi, WeT_lo,
                                                     enc_b, pre_enc, G4);
    mma_gemm<<<dim3(16, G4 / 128), 256, gemm_smem>>>(Ad_hi, Ad_lo, WdT_hi, WdT_lo,
                                                     dec_b, pre_dec, G4);

    // Full recurrence in one persistent kernel
    lstm_persist<<<NCTA, NTHR, lstm_smem>>>(
        pre_enc, pre_dec,
        enc_W + (size_t)DD * G4, dec_W + (size_t)DD * G4,
        len_enc, len_dec, hbuf, hs);

    // Split hs, then projection on tensor cores: logits = hs @ proj_W
    split_convert<<<(BSZ * TY * DD) / 256, 256>>>(hs, Ah_hi, Ah_lo);
    mma_gemm<<<dim3(16, VV / 128), 256, gemm_smem>>>(Ah_hi, Ah_lo, Bt_hi, Bt_lo,
                                                     nullptr, out, VV);
}

// round 7
// speedup vs baseline: 2.7659x; 1.1313x over previous
#include <cuda_runtime.h>
#include <cuda_bf16.h>
#include <math.h>
#include <stdint.h>

// Problem constants
#define BSZ 32
#define TX  64
#define TY  64
#define DD  512
#define HH  512
#define G4  2048   // 4*H
#define VV  32000

#define NCTA 128   // persistent LSTM CTAs
#define NTHR 256

// ---------------- scratch (device globals; no allocation allowed) ----------------
__device__ float g_pre_enc[TX * BSZ * G4];
__device__ float g_pre_dec[TY * BSZ * G4];
__device__ float g_hbuf[2][BSZ * HH];
__device__ float g_hs[BSZ * TY * HH];
__device__ unsigned g_bcount;
__device__ unsigned g_bgen;
__device__ int g_map[BSZ * TY];     // compact row -> original (b*64+t), -1 = pad
__device__ int g_nvalid;            // number of valid decoder rows

// split-bf16 operands (K-major, K=512 columns)
__device__ __nv_bfloat16 g_Bt_hi[VV * DD],  g_Bt_lo[VV * DD];    // proj_W^T  [V][D]
__device__ __nv_bfloat16 g_WeT_hi[G4 * DD], g_WeT_lo[G4 * DD];   // enc Wx^T  [4H][D]
__device__ __nv_bfloat16 g_WdT_hi[G4 * DD], g_WdT_lo[G4 * DD];   // dec Wx^T  [4H][D]
__device__ __nv_bfloat16 g_Ae_hi[TX * BSZ * DD], g_Ae_lo[TX * BSZ * DD];
__device__ __nv_bfloat16 g_Ad_hi[TY * BSZ * DD], g_Ad_lo[TY * BSZ * DD];
__device__ __nv_bfloat16 g_Ah_hi[BSZ * TY * DD], g_Ah_lo[BSZ * TY * DD];

// ======================= helpers =======================
__device__ __forceinline__ uint32_t smem_u32(const void* p) {
    uint32_t a;
    asm("{ .reg .u64 t; cvta.to.shared.u64 t, %1; cvt.u32.u64 %0, t; }" : "=r"(a) : "l"(p));
    return a;
}

#define LDSM4(r, addr) \
    asm volatile("ldmatrix.sync.aligned.m8n8.x4.shared.b16 {%0,%1,%2,%3}, [%4];" \
        : "=r"((r)[0]), "=r"((r)[1]), "=r"((r)[2]), "=r"((r)[3]) : "r"(addr))

#define MMA16816(d, a, b0, b1) \
    asm volatile("mma.sync.aligned.m16n8k16.row.col.f32.bf16.bf16.f32 " \
        "{%0,%1,%2,%3}, {%4,%5,%6,%7}, {%8,%9}, {%0,%1,%2,%3};" \
        : "+f"((d)[0]), "+f"((d)[1]), "+f"((d)[2]), "+f"((d)[3]) \
        : "r"((a)[0]), "r"((a)[1]), "r"((a)[2]), "r"((a)[3]), "r"(b0), "r"(b1))

#define CP_ASYNC16(dst, src) \
    asm volatile("cp.async.cg.shared.global [%0], [%1], 16;" :: "r"(dst), "l"(src))
#define CP_COMMIT()  asm volatile("cp.async.commit_group;" ::: "memory")
#define CP_WAIT(n)   asm volatile("cp.async.wait_group %0;" :: "n"(n) : "memory")

// =====================================================================
// Split-bf16 tensor-core GEMM via mma.sync (HMMA):
//   C[M,N] = (Ahi+Alo)[M,512] @ (Bhi+Blo)[N,512]^T  (+bias)
// CTA: 128x128 tile, BK=64, 3-stage cp.async pipeline (3 x 64KB smem),
// single __syncthreads per mainloop iter. 8 warps = 4(M) x 2(N).
// If map != null: A rows are compacted; CTAs with m0 >= *nvalidp exit,
// output row r scatters to map[r] (skipped when -1; out pre-zeroed).
// =====================================================================
__global__ __launch_bounds__(256, 1)
void mma_gemm(const __nv_bfloat16* __restrict__ Ahi, const __nv_bfloat16* __restrict__ Alo,
              const __nv_bfloat16* __restrict__ Bhi, const __nv_bfloat16* __restrict__ Blo,
              const float* __restrict__ bias, float* __restrict__ C, int N,
              const int* __restrict__ map, const int* __restrict__ nvalidp)
{
    const int m0 = blockIdx.x * 128;
    const int n0 = blockIdx.y * 128;
    if (map && m0 >= *nvalidp) return;      // whole tile past valid rows

    extern __shared__ char smc[];
    const uint32_t sbase = smem_u32(smc);

    const int tid  = threadIdx.x;
    const int wid  = tid >> 5;
    const int lane = tid & 31;
    const int wm = (wid & 3) * 32;    // warp M offset in tile
    const int wn = (wid >> 2) * 64;   // warp N offset in tile

    const __nv_bfloat16* srcs[4] = { Ahi, Alo, Bhi, Blo };
    const int rb[4] = { m0, m0, n0, n0 };

    // per-thread load slots: unit index i = tid + q*256 ; r = i>>3, u = i&7
    uint32_t dsts[4];
    const __nv_bfloat16* gsrc[4][4];
#pragma unroll
    for (int q = 0; q < 4; q++) {
        const int i = tid + q * 256;
        const int r = i >> 3, u = i & 7;
        dsts[q] = (uint32_t)(r * 128 + ((u ^ (r & 7)) << 4));
#pragma unroll
        for (int t4 = 0; t4 < 4; t4++)
            gsrc[t4][q] = srcs[t4] + (size_t)(rb[t4] + r) * DD + u * 8;
    }

    float acc[2][8][4];
#pragma unroll
    for (int mt = 0; mt < 2; mt++)
#pragma unroll
        for (int nt = 0; nt < 8; nt++)
#pragma unroll
            for (int e = 0; e < 4; e++) acc[mt][nt][e] = 0.f;

    // ---- prologue: prefetch stages 0 and 1 ----
#pragma unroll
    for (int s = 0; s < 2; s++) {
        const uint32_t sb = sbase + (uint32_t)s * 65536u;
        const int koff = s * 64;
#pragma unroll
        for (int t4 = 0; t4 < 4; t4++)
#pragma unroll
            for (int q = 0; q < 4; q++)
                CP_ASYNC16(sb + t4 * 16384 + dsts[q], gsrc[t4][q] + koff);
        CP_COMMIT();
    }

    const int lrow15 = lane & 15;
    const int lhalf  = lane >> 4;

    int cs = 0;   // compute stage (it mod 3)
    for (int it = 0; it < 8; it++) {
        if (it < 7) { CP_WAIT(1); } else { CP_WAIT(0); }
        __syncthreads();

        // issue stage it+2 (safe: all warps finished reading this buffer in it-1)
        if (it + 2 < 8) {
            int ps = cs + 2; if (ps >= 3) ps -= 3;
            const uint32_t sb = sbase + (uint32_t)ps * 65536u;
            const int koff = (it + 2) * 64;
#pragma unroll
            for (int t4 = 0; t4 < 4; t4++)
#pragma unroll
                for (int q = 0; q < 4; q++)
                    CP_ASYNC16(sb + t4 * 16384 + dsts[q], gsrc[t4][q] + koff);
            CP_COMMIT();
        }

        const uint32_t B = sbase + (uint32_t)cs * 65536u;

#pragma unroll
        for (int j = 0; j < 4; j++) {   // k16 step within BK=64
            uint32_t ah[2][4], al[2][4];
            uint32_t bh[4][4], bl[4][4];
#pragma unroll
            for (int mt = 0; mt < 2; mt++) {
                const int row = wm + mt * 16 + lrow15;
                const int unit = j * 2 + lhalf;
                const uint32_t addr = B + row * 128 + (((unit ^ (row & 7))) << 4);
                LDSM4(ah[mt], addr);
                LDSM4(al[mt], addr + 16384);
            }
#pragma unroll
            for (int g = 0; g < 4; g++) {
                const int row = wn + g * 16 + lrow15;
                const int unit = j * 2 + lhalf;
                const uint32_t addr = B + 32768 + row * 128 + (((unit ^ (row & 7))) << 4);
                LDSM4(bh[g], addr);
                LDSM4(bl[g], addr + 16384);
            }
#pragma unroll
            for (int mt = 0; mt < 2; mt++)
#pragma unroll
                for (int nt = 0; nt < 8; nt++) {
                    const int g = nt >> 1, o = nt & 1;
                    MMA16816(acc[mt][nt], ah[mt], bh[g][o], bh[g][o + 2]); // hi*hi
                    MMA16816(acc[mt][nt], ah[mt], bl[g][o], bl[g][o + 2]); // hi*lo
                    MMA16816(acc[mt][nt], al[mt], bh[g][o], bh[g][o + 2]); // lo*hi
                }
        }
        cs++; if (cs == 3) cs = 0;
    }

    // ---- epilogue (optionally scattered through map) ----
    const int erow = wm + (lane >> 2);
    const int ec = n0 + wn + (lane & 3) * 2;
#pragma unroll
    for (int mt = 0; mt < 2; mt++) {
        const int r0 = m0 + erow + mt * 16;
        const int r1 = r0 + 8;
        const int o0 = map ? map[r0] : r0;
        const int o1 = map ? map[r1] : r1;
#pragma unroll
        for (int nt = 0; nt < 8; nt++) {
            const int col = ec + nt * 8;
            float b0 = 0.f, b1 = 0.f;
            if (bias) { b0 = bias[col]; b1 = bias[col + 1]; }
            if (o0 >= 0) {
                float* p0 = C + (size_t)o0 * N + col;
                p0[0] = acc[mt][nt][0] + b0;
                p0[1] = acc[mt][nt][1] + b1;
            }
            if (o1 >= 0) {
                float* p1 = C + (size_t)o1 * N + col;
                p1[0] = acc[mt][nt][2] + b0;
                p1[1] = acc[mt][nt][3] + b1;
            }
        }
    }
}

// =====================================================================
// Build compact row map from len_dec: rows (b,t) with t < len_dec[b],
// ordered by (b,t). map[j] = b*64+t for j < nvalid, else -1.
// =====================================================================
__global__ void build_map(const int* __restrict__ len_dec,
                          int* __restrict__ map, int* __restrict__ nvalid)
{
    __shared__ int off[BSZ];
    const int tid = threadIdx.x;
    if (tid == 0) {
        int acc = 0;
        for (int b = 0; b < BSZ; b++) {
            off[b] = acc;
            int L = len_dec[b];
            if (L < 0) L = 0;
            if (L > TY) L = TY;
            acc += L;
        }
        *nvalid = acc;
    }
    __syncthreads();
    for (int i = tid; i < BSZ * TY; i += blockDim.x) map[i] = -1;
    __syncthreads();
    for (int b = 0; b < BSZ; b++) {
        int L = len_dec[b];
        if (L > TY) L = TY;
        for (int t = tid; t < L; t += blockDim.x)
            map[off[b] + t] = b * TY + t;
    }
}

// Compact + split hs: compact row j <- hs[map[j]], zeros for pad rows.
__global__ void split_convert_compact(const float* __restrict__ src,
                                      const int* __restrict__ map,
                                      __nv_bfloat16* __restrict__ hi,
                                      __nv_bfloat16* __restrict__ lo)
{
    const int i = blockIdx.x * 256 + threadIdx.x;
    const int j = i >> 9, k = i & 511;
    const int s = map[j];
    const float v = (s >= 0) ? src[(size_t)s * DD + k] : 0.f;
    const __nv_bfloat16 h = __float2bfloat16(v);
    hi[i] = h;
    lo[i] = __float2bfloat16(v - __bfloat162float(h));
}

// =====================================================================
// Transpose + split:  src[K=512][N] f32  ->  hi/lo [N][512] bf16
// =====================================================================
__global__ void transpose_split(const float* __restrict__ src, int N,
                                __nv_bfloat16* __restrict__ hi, __nv_bfloat16* __restrict__ lo)
{
    __shared__ float t[32][33];
    const int tx = threadIdx.x & 31, ty = threadIdx.x >> 5;
    const int n = blockIdx.x * 32 + tx;
    const int kb = blockIdx.y * 32;
#pragma unroll
    for (int r = 0; r < 32; r += 8)
        t[ty + r][tx] = src[(size_t)(kb + ty + r) * N + n];
    __syncthreads();
#pragma unroll
    for (int r = 0; r < 32; r += 8) {
        const int nn = blockIdx.x * 32 + ty + r;
        const int kk = kb + tx;
        const float v = t[tx][ty + r];
        const __nv_bfloat16 h = __float2bfloat16(v);
        hi[(size_t)nn * DD + kk] = h;
        lo[(size_t)nn * DD + kk] = __float2bfloat16(v - __bfloat162float(h));
    }
}

// Embedding gather + split: row m (b=m&31, t=m>>5) <- E[ids[b*idxT+t]]
__global__ void gather_split(const float* __restrict__ E, const int* __restrict__ ids, int idxT,
                             __nv_bfloat16* __restrict__ hi, __nv_bfloat16* __restrict__ lo)
{
    const int i = blockIdx.x * 256 + threadIdx.x;
    const int row = i >> 9, k = i & 511;
    const int b = row & 31, t = row >> 5;
    const float v = E[(size_t)ids[b * idxT + t] * DD + k];
    const __nv_bfloat16 h = __float2bfloat16(v);
    hi[i] = h;
    lo[i] = __float2bfloat16(v - __bfloat162float(h));
}

// =====================================================================
// Software grid barrier (all NCTA CTAs co-resident)
// =====================================================================
__device__ __forceinline__ void grid_barrier()
{
    __syncthreads();
    if (threadIdx.x == 0) {
        unsigned gen = *(volatile unsigned*)&g_bgen;
        __threadfence();
        unsigned t = atomicAdd(&g_bcount, 1);
        if (t == NCTA - 1) {
            atomicExch(&g_bcount, 0);
            __threadfence();
            atomicAdd(&g_bgen, 1);
        } else {
            while (*(volatile unsigned*)&g_bgen == gen) { }
        }
        __threadfence();
    }
    __syncthreads();
}

// =====================================================================
// Persistent LSTM (proven): all 128 timesteps, one launch.
// =====================================================================
__global__ __launch_bounds__(NTHR, 1)
void lstm_persist(const float* __restrict__ pre_enc, const float* __restrict__ pre_dec,
                  const float* __restrict__ enc_Wh, const float* __restrict__ dec_Wh,
                  const int* __restrict__ len_enc, const int* __restrict__ len_dec,
                  float* __restrict__ hbuf, float* __restrict__ hs)
{
    extern __shared__ float smf[];
    float* whs  = smf;                    // 16*520
    float* hsm  = smf + 16 * 520;         // 32*516
    float* zbuf = hsm + 32 * 516;         // 32*17

    const int tid = threadIdx.x;
    const int cta = blockIdx.x;
    const int zc  = tid & 15;
    const int bb  = tid >> 4;
    const int b0  = bb * 2, b1 = bb * 2 + 1;

    float c_reg = 0.f;

    for (int phase = 0; phase < 2; phase++) {
        const float* Wh  = phase ? dec_Wh  : enc_Wh;
        const float* pre = phase ? pre_dec : pre_enc;
        const int*   len = phase ? len_dec : len_enc;

        for (int i = tid; i < 16 * 512; i += NTHR) {
            int z = i >> 9, k = i & 511;
            whs[z * 520 + k] =
                __ldg(&Wh[(size_t)k * G4 + (z >> 2) * 512 + cta * 4 + (z & 3)]);
        }
        __syncthreads();

        for (int s = 0; s < 64; s++) {
            const int sigma = phase * 64 + s;
            const float* hin  = hbuf + (sigma & 1) * (BSZ * HH);
            float*       hout = hbuf + ((sigma + 1) & 1) * (BSZ * HH);

            for (int i = tid; i < (BSZ * HH) / 4; i += NTHR) {
                int b = i >> 7, k4 = i & 127;
                float4 v = __ldcg((const float4*)&hin[b * HH + k4 * 4]);
                *(float4*)&hsm[b * 516 + k4 * 4] = v;
            }
            __syncthreads();

            float acc0 = 0.f, acc1 = 0.f;
            const float* wr  = &whs[zc * 520];
            const float* h0r = &hsm[b0 * 516];
            const float* h1r = &hsm[b1 * 516];
#pragma unroll 4
            for (int k = 0; k < 512; k += 4) {
                float4 w4 = *(const float4*)&wr[k];
                float4 ha = *(const float4*)&h0r[k];
                float4 hb = *(const float4*)&h1r[k];
                acc0 += ha.x * w4.x + ha.y * w4.y + ha.z * w4.z + ha.w * w4.w;
                acc1 += hb.x * w4.x + hb.y * w4.y + hb.z * w4.z + hb.w * w4.w;
            }
            zbuf[b0 * 17 + zc] = acc0;
            zbuf[b1 * 17 + zc] = acc1;
            __syncthreads();

            if (tid < 128) {
                const int b  = tid >> 2;
                const int hc = tid & 3;
                const int n  = cta * 4 + hc;
                const float* pz = pre + (size_t)s * BSZ * G4 + (size_t)b * G4 + n;

                float zi = pz[0]    + zbuf[b * 17 + hc];
                float zj = pz[512]  + zbuf[b * 17 + 4 + hc];
                float zf = pz[1024] + zbuf[b * 17 + 8 + hc];
                float zo = pz[1536] + zbuf[b * 17 + 12 + hc];

                float fg = 1.f / (1.f + expf(-(zf + 1.0f)));
                float ig = 1.f / (1.f + expf(-zi));
                float og = 1.f / (1.f + expf(-zo));
                float cn = c_reg * fg + ig * tanhf(zj);
                float hn = tanhf(cn) * og;

                bool m = (s < len[b]);
                float hprev = hsm[b * 516 + n];
                c_reg = m ? cn : c_reg;
                hout[b * HH + n] = m ? hn : hprev;
                if (phase)
                    hs[((size_t)b * TY + s) * HH + n] = m ? hn : 0.f;
            }
            grid_barrier();
        }
    }
}

// =====================================================================
// Host launcher (graph-capturable)
// =====================================================================
extern "C" void kernel_launch(void* const* d_in, const int* in_sizes, int n_in,
                              void* d_out, int out_size)
{
    const int*   enc_ids = (const int*)d_in[0];
    const int*   dec_ids = (const int*)d_in[1];
    const int*   len_enc = (const int*)d_in[2];
    const int*   len_dec = (const int*)d_in[3];
    const float* E       = (const float*)d_in[4];
    const float* enc_W   = (const float*)d_in[5];
    const float* enc_b   = (const float*)d_in[6];
    const float* dec_W   = (const float*)d_in[7];
    const float* dec_b   = (const float*)d_in[8];
    const float* proj_W  = (const float*)d_in[9];
    float*       out     = (float*)d_out;

    float *pre_enc, *pre_dec, *hbuf, *hs;
    int *map, *nvalid;
    cudaGetSymbolAddress((void**)&pre_enc, g_pre_enc);
    cudaGetSymbolAddress((void**)&pre_dec, g_pre_dec);
    cudaGetSymbolAddress((void**)&hbuf,    g_hbuf);
    cudaGetSymbolAddress((void**)&hs,      g_hs);
    cudaGetSymbolAddress((void**)&map,     g_map);
    cudaGetSymbolAddress((void**)&nvalid,  g_nvalid);

    __nv_bfloat16 *Bt_hi, *Bt_lo, *WeT_hi, *WeT_lo, *WdT_hi, *WdT_lo;
    __nv_bfloat16 *Ae_hi, *Ae_lo, *Ad_hi, *Ad_lo, *Ah_hi, *Ah_lo;
    cudaGetSymbolAddress((void**)&Bt_hi,  g_Bt_hi);
    cudaGetSymbolAddress((void**)&Bt_lo,  g_Bt_lo);
    cudaGetSymbolAddress((void**)&WeT_hi, g_WeT_hi);
    cudaGetSymbolAddress((void**)&WeT_lo, g_WeT_lo);
    cudaGetSymbolAddress((void**)&WdT_hi, g_WdT_hi);
    cudaGetSymbolAddress((void**)&WdT_lo, g_WdT_lo);
    cudaGetSymbolAddress((void**)&Ae_hi,  g_Ae_hi);
    cudaGetSymbolAddress((void**)&Ae_lo,  g_Ae_lo);
    cudaGetSymbolAddress((void**)&Ad_hi,  g_Ad_hi);
    cudaGetSymbolAddress((void**)&Ad_lo,  g_Ad_lo);
    cudaGetSymbolAddress((void**)&Ah_hi,  g_Ah_hi);
    cudaGetSymbolAddress((void**)&Ah_lo,  g_Ah_lo);

    const size_t lstm_smem = (16 * 520 + 32 * 516 + 32 * 17) * sizeof(float);
    const size_t gemm_smem = 3 * 4 * 16384;   // 192KB: 3-stage pipeline
    static bool attr_set = false;
    if (!attr_set) {
        cudaFuncSetAttribute(lstm_persist,
                             cudaFuncAttributeMaxDynamicSharedMemorySize, (int)lstm_smem);
        cudaFuncSetAttribute(mma_gemm,
                             cudaFuncAttributeMaxDynamicSharedMemorySize, (int)gemm_smem);
        attr_set = true;
    }

    // Zero output (invalid decoder rows stay zero after scattered projection)
    cudaMemsetAsync(out, 0, (size_t)out_size * sizeof(float), 0);
    cudaMemsetAsync(hbuf, 0, BSZ * HH * sizeof(float), 0);

    // Compact-row map from len_dec
    build_map<<<1, 128>>>(len_dec, map, nvalid);

    // Weight transposes + splits
    transpose_split<<<dim3(VV / 32, DD / 32), 256>>>(proj_W, VV, Bt_hi, Bt_lo);
    transpose_split<<<dim3(G4 / 32, DD / 32), 256>>>(enc_W, G4, WeT_hi, WeT_lo);
    transpose_split<<<dim3(G4 / 32, DD / 32), 256>>>(dec_W, G4, WdT_hi, WdT_lo);

    // Embedding gathers + splits
    gather_split<<<(TX * BSZ * DD) / 256, 256>>>(E, enc_ids, TX, Ae_hi, Ae_lo);
    gather_split<<<(TY * BSZ * DD) / 256, 256>>>(E, dec_ids, TY, Ad_hi, Ad_lo);

    // Pre-activations on tensor cores: pre = emb @ Wx + b   [2048 x 2048]
    mma_gemm<<<dim3(16, G4 / 128), 256, gemm_smem>>>(Ae_hi, Ae_lo, WeT_hi, WeT_lo,
                                                     enc_b, pre_enc, G4, nullptr, nullptr);
    mma_gemm<<<dim3(16, G4 / 128), 256, gemm_smem>>>(Ad_hi, Ad_lo, WdT_hi, WdT_lo,
                                                     dec_b, pre_dec, G4, nullptr, nullptr);

    // Full recurrence in one persistent kernel
    lstm_persist<<<NCTA, NTHR, lstm_smem>>>(
        pre_enc, pre_dec,
        enc_W + (size_t)DD * G4, dec_W + (size_t)DD * G4,
        len_enc, len_dec, hbuf, hs);

    // Compact + split hs, then projection over valid rows only,
    // scattering outputs through the row map (rest of out is zero).
    split_convert_compact<<<(BSZ * TY * DD) / 256, 256>>>(hs, map, Ah_hi, Ah_lo);
    mma_gemm<<<dim3(16, VV / 128), 256, gemm_smem>>>(Ah_hi, Ah_lo, Bt_hi, Bt_lo,
                                                     nullptr, out, VV, map, nvalid);
}

// round 8
// speedup vs baseline: 2.8892x; 1.0446x over previous
#include <cuda_runtime.h>
#include <cuda_bf16.h>
#include <cuda_fp16.h>
#include <math.h>
#include <stdint.h>

// Problem constants
#define BSZ 32
#define TX  64
#define TY  64
#define DD  512
#define HH  512
#define G4  2048   // 4*H
#define VV  32000

#define NCTA 128   // persistent LSTM CTAs
#define NTHR 256

// ---------------- scratch (device globals; no allocation allowed) ----------------
__device__ float g_pre_enc[TX * BSZ * G4];
__device__ float g_pre_dec[TY * BSZ * G4];
__device__ float g_hbuf[2][BSZ * HH];
__device__ float g_hs[BSZ * TY * HH];
__device__ unsigned g_bcount;
__device__ unsigned g_bgen;
__device__ int g_map[BSZ * TY];     // compact row -> original (b*64+t), -1 = pad
__device__ int g_nvalid;            // number of valid decoder rows

// bf16 3-term operands for the pre-activation GEMMs (K-major, K=512)
__device__ __nv_bfloat16 g_WeT_hi[G4 * DD], g_WeT_lo[G4 * DD];   // enc Wx^T  [4H][D]
__device__ __nv_bfloat16 g_WdT_hi[G4 * DD], g_WdT_lo[G4 * DD];   // dec Wx^T  [4H][D]
__device__ __nv_bfloat16 g_Ae_hi[TX * BSZ * DD], g_Ae_lo[TX * BSZ * DD];
__device__ __nv_bfloat16 g_Ad_hi[TY * BSZ * DD], g_Ad_lo[TY * BSZ * DD];

// fp16 2-term operands for the projection GEMM
__device__ __half g_Bt_h[VV * DD];                                // proj_W^T  [V][D], hi only
__device__ __half g_Ah_hi[BSZ * TY * DD], g_Ah_lo[BSZ * TY * DD]; // hs split fp16

// ======================= helpers =======================
__device__ __forceinline__ uint32_t smem_u32(const void* p) {
    uint32_t a;
    asm("{ .reg .u64 t; cvta.to.shared.u64 t, %1; cvt.u32.u64 %0, t; }" : "=r"(a) : "l"(p));
    return a;
}

#define LDSM4(r, addr) \
    asm volatile("ldmatrix.sync.aligned.m8n8.x4.shared.b16 {%0,%1,%2,%3}, [%4];" \
        : "=r"((r)[0]), "=r"((r)[1]), "=r"((r)[2]), "=r"((r)[3]) : "r"(addr))

#define MMA_BF16(d, a, b0, b1) \
    asm volatile("mma.sync.aligned.m16n8k16.row.col.f32.bf16.bf16.f32 " \
        "{%0,%1,%2,%3}, {%4,%5,%6,%7}, {%8,%9}, {%0,%1,%2,%3};" \
        : "+f"((d)[0]), "+f"((d)[1]), "+f"((d)[2]), "+f"((d)[3]) \
        : "r"((a)[0]), "r"((a)[1]), "r"((a)[2]), "r"((a)[3]), "r"(b0), "r"(b1))

#define MMA_F16(d, a, b0, b1) \
    asm volatile("mma.sync.aligned.m16n8k16.row.col.f32.f16.f16.f32 " \
        "{%0,%1,%2,%3}, {%4,%5,%6,%7}, {%8,%9}, {%0,%1,%2,%3};" \
        : "+f"((d)[0]), "+f"((d)[1]), "+f"((d)[2]), "+f"((d)[3]) \
        : "r"((a)[0]), "r"((a)[1]), "r"((a)[2]), "r"((a)[3]), "r"(b0), "r"(b1))

#define CP_ASYNC16(dst, src) \
    asm volatile("cp.async.cg.shared.global [%0], [%1], 16;" :: "r"(dst), "l"(src))
#define CP_COMMIT()  asm volatile("cp.async.commit_group;" ::: "memory")
#define CP_WAIT(n)   asm volatile("cp.async.wait_group %0;" :: "n"(n) : "memory")

// =====================================================================
// 3-term split-bf16 GEMM (pre-activations):
//   C[M,N] = (Ahi+Alo)[M,512] @ (Bhi+Blo)[N,512]^T + bias
// CTA 128x128, BK=64, 3-stage cp.async pipeline (3 x 64KB smem).
// =====================================================================
__global__ __launch_bounds__(256, 1)
void mma_gemm(const __nv_bfloat16* __restrict__ Ahi, const __nv_bfloat16* __restrict__ Alo,
              const __nv_bfloat16* __restrict__ Bhi, const __nv_bfloat16* __restrict__ Blo,
              const float* __restrict__ bias, float* __restrict__ C, int N)
{
    extern __shared__ char smc[];
    const uint32_t sbase = smem_u32(smc);

    const int tid  = threadIdx.x;
    const int wid  = tid >> 5;
    const int lane = tid & 31;
    const int m0 = blockIdx.x * 128;
    const int n0 = blockIdx.y * 128;
    const int wm = (wid & 3) * 32;
    const int wn = (wid >> 2) * 64;

    const __nv_bfloat16* srcs[4] = { Ahi, Alo, Bhi, Blo };
    const int rb[4] = { m0, m0, n0, n0 };

    uint32_t dsts[4];
    const __nv_bfloat16* gsrc[4][4];
#pragma unroll
    for (int q = 0; q < 4; q++) {
        const int i = tid + q * 256;
        const int r = i >> 3, u = i & 7;
        dsts[q] = (uint32_t)(r * 128 + ((u ^ (r & 7)) << 4));
#pragma unroll
        for (int t4 = 0; t4 < 4; t4++)
            gsrc[t4][q] = srcs[t4] + (size_t)(rb[t4] + r) * DD + u * 8;
    }

    float acc[2][8][4];
#pragma unroll
    for (int mt = 0; mt < 2; mt++)
#pragma unroll
        for (int nt = 0; nt < 8; nt++)
#pragma unroll
            for (int e = 0; e < 4; e++) acc[mt][nt][e] = 0.f;

#pragma unroll
    for (int s = 0; s < 2; s++) {
        const uint32_t sb = sbase + (uint32_t)s * 65536u;
        const int koff = s * 64;
#pragma unroll
        for (int t4 = 0; t4 < 4; t4++)
#pragma unroll
            for (int q = 0; q < 4; q++)
                CP_ASYNC16(sb + t4 * 16384 + dsts[q], gsrc[t4][q] + koff);
        CP_COMMIT();
    }

    const int lrow15 = lane & 15;
    const int lhalf  = lane >> 4;

    int cs = 0;
    for (int it = 0; it < 8; it++) {
        if (it < 7) { CP_WAIT(1); } else { CP_WAIT(0); }
        __syncthreads();

        if (it + 2 < 8) {
            int ps = cs + 2; if (ps >= 3) ps -= 3;
            const uint32_t sb = sbase + (uint32_t)ps * 65536u;
            const int koff = (it + 2) * 64;
#pragma unroll
            for (int t4 = 0; t4 < 4; t4++)
#pragma unroll
                for (int q = 0; q < 4; q++)
                    CP_ASYNC16(sb + t4 * 16384 + dsts[q], gsrc[t4][q] + koff);
            CP_COMMIT();
        }

        const uint32_t B = sbase + (uint32_t)cs * 65536u;

#pragma unroll
        for (int j = 0; j < 4; j++) {
            uint32_t ah[2][4], al[2][4];
            uint32_t bh[4][4], bl[4][4];
#pragma unroll
            for (int mt = 0; mt < 2; mt++) {
                const int row = wm + mt * 16 + lrow15;
                const int unit = j * 2 + lhalf;
                const uint32_t addr = B + row * 128 + (((unit ^ (row & 7))) << 4);
                LDSM4(ah[mt], addr);
                LDSM4(al[mt], addr + 16384);
            }
#pragma unroll
            for (int g = 0; g < 4; g++) {
                const int row = wn + g * 16 + lrow15;
                const int unit = j * 2 + lhalf;
                const uint32_t addr = B + 32768 + row * 128 + (((unit ^ (row & 7))) << 4);
                LDSM4(bh[g], addr);
                LDSM4(bl[g], addr + 16384);
            }
#pragma unroll
            for (int mt = 0; mt < 2; mt++)
#pragma unroll
                for (int nt = 0; nt < 8; nt++) {
                    const int g = nt >> 1, o = nt & 1;
                    MMA_BF16(acc[mt][nt], ah[mt], bh[g][o], bh[g][o + 2]);
                    MMA_BF16(acc[mt][nt], ah[mt], bl[g][o], bl[g][o + 2]);
                    MMA_BF16(acc[mt][nt], al[mt], bh[g][o], bh[g][o + 2]);
                }
        }
        cs++; if (cs == 3) cs = 0;
    }

    const int erow = wm + (lane >> 2);
    const int ec = n0 + wn + (lane & 3) * 2;
#pragma unroll
    for (int mt = 0; mt < 2; mt++) {
        const int r0 = m0 + erow + mt * 16;
#pragma unroll
        for (int nt = 0; nt < 8; nt++) {
            const int col = ec + nt * 8;
            float b0 = 0.f, b1 = 0.f;
            if (bias) { b0 = bias[col]; b1 = bias[col + 1]; }
            float* p0 = C + (size_t)r0 * N + col;
            float* p1 = C + (size_t)(r0 + 8) * N + col;
            p0[0] = acc[mt][nt][0] + b0;
            p0[1] = acc[mt][nt][1] + b1;
            p1[0] = acc[mt][nt][2] + b0;
            p1[1] = acc[mt][nt][3] + b1;
        }
    }
}

// =====================================================================
// 2-term split-fp16 GEMM (projection):
//   C[M,N] = (Ahi+Alo)_fp16[M,512] @ Bh_fp16[N,512]^T
// 3 operand tiles (48KB/stage), 3-stage pipeline. A rows compacted:
// CTAs with m0 >= *nvalidp exit; row r scatters to map[r] (-1 skipped).
// Error = A @ (B - fp16(B)) ~ 1.4e-4 aggregate.
// =====================================================================
__global__ __launch_bounds__(256, 1)
void mma_gemm_h2(const __half* __restrict__ Ahi, const __half* __restrict__ Alo,
                 const __half* __restrict__ Bh,
                 float* __restrict__ C, int N,
                 const int* __restrict__ map, const int* __restrict__ nvalidp)
{
    const int m0 = blockIdx.x * 128;
    const int n0 = blockIdx.y * 128;
    if (m0 >= *nvalidp) return;

    extern __shared__ char smc[];
    const uint32_t sbase = smem_u32(smc);

    const int tid  = threadIdx.x;
    const int wid  = tid >> 5;
    const int lane = tid & 31;
    const int wm = (wid & 3) * 32;
    const int wn = (wid >> 2) * 64;

    const __half* srcs[3] = { Ahi, Alo, Bh };
    const int rb[3] = { m0, m0, n0 };

    uint32_t dsts[4];
    const __half* gsrc[3][4];
#pragma unroll
    for (int q = 0; q < 4; q++) {
        const int i = tid + q * 256;
        const int r = i >> 3, u = i & 7;
        dsts[q] = (uint32_t)(r * 128 + ((u ^ (r & 7)) << 4));
#pragma unroll
        for (int t3 = 0; t3 < 3; t3++)
            gsrc[t3][q] = srcs[t3] + (size_t)(rb[t3] + r) * DD + u * 8;
    }

    float acc[2][8][4];
#pragma unroll
    for (int mt = 0; mt < 2; mt++)
#pragma unroll
        for (int nt = 0; nt < 8; nt++)
#pragma unroll
            for (int e = 0; e < 4; e++) acc[mt][nt][e] = 0.f;

    // stage stride = 3 tiles x 16KB = 48KB
#pragma unroll
    for (int s = 0; s < 2; s++) {
        const uint32_t sb = sbase + (uint32_t)s * 49152u;
        const int koff = s * 64;
#pragma unroll
        for (int t3 = 0; t3 < 3; t3++)
#pragma unroll
            for (int q = 0; q < 4; q++)
                CP_ASYNC16(sb + t3 * 16384 + dsts[q], gsrc[t3][q] + koff);
        CP_COMMIT();
    }

    const int lrow15 = lane & 15;
    const int lhalf  = lane >> 4;

    int cs = 0;
    for (int it = 0; it < 8; it++) {
        if (it < 7) { CP_WAIT(1); } else { CP_WAIT(0); }
        __syncthreads();

        if (it + 2 < 8) {
            int ps = cs + 2; if (ps >= 3) ps -= 3;
            const uint32_t sb = sbase + (uint32_t)ps * 49152u;
            const int koff = (it + 2) * 64;
#pragma unroll
            for (int t3 = 0; t3 < 3; t3++)
#pragma unroll
                for (int q = 0; q < 4; q++)
                    CP_ASYNC16(sb + t3 * 16384 + dsts[q], gsrc[t3][q] + koff);
            CP_COMMIT();
        }

        const uint32_t B = sbase + (uint32_t)cs * 49152u;

#pragma unroll
        for (int j = 0; j < 4; j++) {
            uint32_t ah[2][4], al[2][4];
            uint32_t bh[4][4];
#pragma unroll
            for (int mt = 0; mt < 2; mt++) {
                const int row = wm + mt * 16 + lrow15;
                const int unit = j * 2 + lhalf;
                const uint32_t addr = B + row * 128 + (((unit ^ (row & 7))) << 4);
                LDSM4(ah[mt], addr);
                LDSM4(al[mt], addr + 16384);
            }
#pragma unroll
            for (int g = 0; g < 4; g++) {
                const int row = wn + g * 16 + lrow15;
                const int unit = j * 2 + lhalf;
                const uint32_t addr = B + 32768 + row * 128 + (((unit ^ (row & 7))) << 4);
                LDSM4(bh[g], addr);
            }
#pragma unroll
            for (int mt = 0; mt < 2; mt++)
#pragma unroll
                for (int nt = 0; nt < 8; nt++) {
                    const int g = nt >> 1, o = nt & 1;
                    MMA_F16(acc[mt][nt], ah[mt], bh[g][o], bh[g][o + 2]);  // hi @ B
                    MMA_F16(acc[mt][nt], al[mt], bh[g][o], bh[g][o + 2]);  // lo @ B
                }
        }
        cs++; if (cs == 3) cs = 0;
    }

    // epilogue, scattered through map (out pre-zeroed)
    const int erow = wm + (lane >> 2);
    const int ec = n0 + wn + (lane & 3) * 2;
#pragma unroll
    for (int mt = 0; mt < 2; mt++) {
        const int r0 = m0 + erow + mt * 16;
        const int r1 = r0 + 8;
        const int o0 = map[r0];
        const int o1 = map[r1];
#pragma unroll
        for (int nt = 0; nt < 8; nt++) {
            const int col = ec + nt * 8;
            if (o0 >= 0) {
                float* p0 = C + (size_t)o0 * N + col;
                p0[0] = acc[mt][nt][0];
                p0[1] = acc[mt][nt][1];
            }
            if (o1 >= 0) {
                float* p1 = C + (size_t)o1 * N + col;
                p1[0] = acc[mt][nt][2];
                p1[1] = acc[mt][nt][3];
            }
        }
    }
}

// =====================================================================
// Build compact row map from len_dec.
// =====================================================================
__global__ void build_map(const int* __restrict__ len_dec,
                          int* __restrict__ map, int* __restrict__ nvalid)
{
    __shared__ int off[BSZ];
    const int tid = threadIdx.x;
    if (tid == 0) {
        int acc = 0;
        for (int b = 0; b < BSZ; b++) {
            off[b] = acc;
            int L = len_dec[b];
            if (L < 0) L = 0;
            if (L > TY) L = TY;
            acc += L;
        }
        *nvalid = acc;
    }
    __syncthreads();
    for (int i = tid; i < BSZ * TY; i += blockDim.x) map[i] = -1;
    __syncthreads();
    for (int b = 0; b < BSZ; b++) {
        int L = len_dec[b];
        if (L > TY) L = TY;
        for (int t = tid; t < L; t += blockDim.x)
            map[off[b] + t] = b * TY + t;
    }
}

// Compact + split hs into fp16 hi/lo: compact row j <- hs[map[j]], pad rows = 0.
__global__ void split_compact_f16(const float* __restrict__ src,
                                  const int* __restrict__ map,
                                  __half* __restrict__ hi, __half* __restrict__ lo)
{
    const int i = blockIdx.x * 256 + threadIdx.x;
    const int j = i >> 9, k = i & 511;
    const int s = map[j];
    const float v = (s >= 0) ? src[(size_t)s * DD + k] : 0.f;
    const __half h = __float2half(v);
    hi[i] = h;
    lo[i] = __float2half(v - __half2float(h));
}

// Transpose + single fp16:  src[K=512][N] f32  ->  h [N][512] fp16
__global__ void transpose_f16(const float* __restrict__ src, int N,
                              __half* __restrict__ dst)
{
    __shared__ float t[32][33];
    const int tx = threadIdx.x & 31, ty = threadIdx.x >> 5;
    const int n = blockIdx.x * 32 + tx;
    const int kb = blockIdx.y * 32;
#pragma unroll
    for (int r = 0; r < 32; r += 8)
        t[ty + r][tx] = src[(size_t)(kb + ty + r) * N + n];
    __syncthreads();
#pragma unroll
    for (int r = 0; r < 32; r += 8) {
        const int nn = blockIdx.x * 32 + ty + r;
        const int kk = kb + tx;
        dst[(size_t)nn * DD + kk] = __float2half(t[tx][ty + r]);
    }
}

// Transpose + split bf16:  src[K=512][N] f32  ->  hi/lo [N][512] bf16
__global__ void transpose_split(const float* __restrict__ src, int N,
                                __nv_bfloat16* __restrict__ hi, __nv_bfloat16* __restrict__ lo)
{
    __shared__ float t[32][33];
    const int tx = threadIdx.x & 31, ty = threadIdx.x >> 5;
    const int n = blockIdx.x * 32 + tx;
    const int kb = blockIdx.y * 32;
#pragma unroll
    for (int r = 0; r < 32; r += 8)
        t[ty + r][tx] = src[(size_t)(kb + ty + r) * N + n];
    __syncthreads();
#pragma unroll
    for (int r = 0; r < 32; r += 8) {
        const int nn = blockIdx.x * 32 + ty + r;
        const int kk = kb + tx;
        const float v = t[tx][ty + r];
        const __nv_bfloat16 h = __float2bfloat16(v);
        hi[(size_t)nn * DD + kk] = h;
        lo[(size_t)nn * DD + kk] = __float2bfloat16(v - __bfloat162float(h));
    }
}

// Embedding gather + split bf16
__global__ void gather_split(const float* __restrict__ E, const int* __restrict__ ids, int idxT,
                             __nv_bfloat16* __restrict__ hi, __nv_bfloat16* __restrict__ lo)
{
    const int i = blockIdx.x * 256 + threadIdx.x;
    const int row = i >> 9, k = i & 511;
    const int b = row & 31, t = row >> 5;
    const float v = E[(size_t)ids[b * idxT + t] * DD + k];
    const __nv_bfloat16 h = __float2bfloat16(v);
    hi[i] = h;
    lo[i] = __float2bfloat16(v - __bfloat162float(h));
}

// =====================================================================
// Software grid barrier (all NCTA CTAs co-resident)
// =====================================================================
__device__ __forceinline__ void grid_barrier()
{
    __syncthreads();
    if (threadIdx.x == 0) {
        unsigned gen = *(volatile unsigned*)&g_bgen;
        __threadfence();
        unsigned t = atomicAdd(&g_bcount, 1);
        if (t == NCTA - 1) {
            atomicExch(&g_bcount, 0);
            __threadfence();
            atomicAdd(&g_bgen, 1);
        } else {
            while (*(volatile unsigned*)&g_bgen == gen) { }
        }
        __threadfence();
    }
    __syncthreads();
}

// =====================================================================
// Persistent LSTM (proven): all 128 timesteps, one launch.
// =====================================================================
__global__ __launch_bounds__(NTHR, 1)
void lstm_persist(const float* __restrict__ pre_enc, const float* __restrict__ pre_dec,
                  const float* __restrict__ enc_Wh, const float* __restrict__ dec_Wh,
                  const int* __restrict__ len_enc, const int* __restrict__ len_dec,
                  float* __restrict__ hbuf, float* __restrict__ hs)
{
    extern __shared__ float smf[];
    float* whs  = smf;                    // 16*520
    float* hsm  = smf + 16 * 520;         // 32*516
    float* zbuf = hsm + 32 * 516;         // 32*17

    const int tid = threadIdx.x;
    const int cta = blockIdx.x;
    const int zc  = tid & 15;
    const int bb  = tid >> 4;
    const int b0  = bb * 2, b1 = bb * 2 + 1;

    float c_reg = 0.f;

    for (int phase = 0; phase < 2; phase++) {
        const float* Wh  = phase ? dec_Wh  : enc_Wh;
        const float* pre = phase ? pre_dec : pre_enc;
        const int*   len = phase ? len_dec : len_enc;

        for (int i = tid; i < 16 * 512; i += NTHR) {
            int z = i >> 9, k = i & 511;
            whs[z * 520 + k] =
                __ldg(&Wh[(size_t)k * G4 + (z >> 2) * 512 + cta * 4 + (z & 3)]);
        }
        __syncthreads();

        for (int s = 0; s < 64; s++) {
            const int sigma = phase * 64 + s;
            const float* hin  = hbuf + (sigma & 1) * (BSZ * HH);
            float*       hout = hbuf + ((sigma + 1) & 1) * (BSZ * HH);

            for (int i = tid; i < (BSZ * HH) / 4; i += NTHR) {
                int b = i >> 7, k4 = i & 127;
                float4 v = __ldcg((const float4*)&hin[b * HH + k4 * 4]);
                *(float4*)&hsm[b * 516 + k4 * 4] = v;
            }
            __syncthreads();

            float acc0 = 0.f, acc1 = 0.f;
            const float* wr  = &whs[zc * 520];
            const float* h0r = &hsm[b0 * 516];
            const float* h1r = &hsm[b1 * 516];
#pragma unroll 4
            for (int k = 0; k < 512; k += 4) {
                float4 w4 = *(const float4*)&wr[k];
                float4 ha = *(const float4*)&h0r[k];
                float4 hb = *(const float4*)&h1r[k];
                acc0 += ha.x * w4.x + ha.y * w4.y + ha.z * w4.z + ha.w * w4.w;
                acc1 += hb.x * w4.x + hb.y * w4.y + hb.z * w4.z + hb.w * w4.w;
            }
            zbuf[b0 * 17 + zc] = acc0;
            zbuf[b1 * 17 + zc] = acc1;
            __syncthreads();

            if (tid < 128) {
                const int b  = tid >> 2;
                const int hc = tid & 3;
                const int n  = cta * 4 + hc;
                const float* pz = pre + (size_t)s * BSZ * G4 + (size_t)b * G4 + n;

                float zi = pz[0]    + zbuf[b * 17 + hc];
                float zj = pz[512]  + zbuf[b * 17 + 4 + hc];
                float zf = pz[1024] + zbuf[b * 17 + 8 + hc];
                float zo = pz[1536] + zbuf[b * 17 + 12 + hc];

                float fg = 1.f / (1.f + expf(-(zf + 1.0f)));
                float ig = 1.f / (1.f + expf(-zi));
                float og = 1.f / (1.f + expf(-zo));
                float cn = c_reg * fg + ig * tanhf(zj);
                float hn = tanhf(cn) * og;

                bool m = (s < len[b]);
                float hprev = hsm[b * 516 + n];
                c_reg = m ? cn : c_reg;
                hout[b * HH + n] = m ? hn : hprev;
                if (phase)
                    hs[((size_t)b * TY + s) * HH + n] = m ? hn : 0.f;
            }
            grid_barrier();
        }
    }
}

// =====================================================================
// Host launcher (graph-capturable)
// =====================================================================
extern "C" void kernel_launch(void* const* d_in, const int* in_sizes, int n_in,
                              void* d_out, int out_size)
{
    const int*   enc_ids = (const int*)d_in[0];
    const int*   dec_ids = (const int*)d_in[1];
    const int*   len_enc = (const int*)d_in[2];
    const int*   len_dec = (const int*)d_in[3];
    const float* E       = (const float*)d_in[4];
    const float* enc_W   = (const float*)d_in[5];
    const float* enc_b   = (const float*)d_in[6];
    const float* dec_W   = (const float*)d_in[7];
    const float* dec_b   = (const float*)d_in[8];
    const float* proj_W  = (const float*)d_in[9];
    float*       out     = (float*)d_out;

    float *pre_enc, *pre_dec, *hbuf, *hs;
    int *map, *nvalid;
    cudaGetSymbolAddress((void**)&pre_enc, g_pre_enc);
    cudaGetSymbolAddress((void**)&pre_dec, g_pre_dec);
    cudaGetSymbolAddress((void**)&hbuf,    g_hbuf);
    cudaGetSymbolAddress((void**)&hs,      g_hs);
    cudaGetSymbolAddress((void**)&map,     g_map);
    cudaGetSymbolAddress((void**)&nvalid,  g_nvalid);

    __nv_bfloat16 *WeT_hi, *WeT_lo, *WdT_hi, *WdT_lo;
    __nv_bfloat16 *Ae_hi, *Ae_lo, *Ad_hi, *Ad_lo;
    __half *Bt_h, *Ah_hi, *Ah_lo;
    cudaGetSymbolAddress((void**)&WeT_hi, g_WeT_hi);
    cudaGetSymbolAddress((void**)&WeT_lo, g_WeT_lo);
    cudaGetSymbolAddress((void**)&WdT_hi, g_WdT_hi);
    cudaGetSymbolAddress((void**)&WdT_lo, g_WdT_lo);
    cudaGetSymbolAddress((void**)&Ae_hi,  g_Ae_hi);
    cudaGetSymbolAddress((void**)&Ae_lo,  g_Ae_lo);
    cudaGetSymbolAddress((void**)&Ad_hi,  g_Ad_hi);
    cudaGetSymbolAddress((void**)&Ad_lo,  g_Ad_lo);
    cudaGetSymbolAddress((void**)&Bt_h,   g_Bt_h);
    cudaGetSymbolAddress((void**)&Ah_hi,  g_Ah_hi);
    cudaGetSymbolAddress((void**)&Ah_lo,  g_Ah_lo);

    const size_t lstm_smem  = (16 * 520 + 32 * 516 + 32 * 17) * sizeof(float);
    const size_t gemm_smem  = 3 * 4 * 16384;   // 192KB (bf16 3-term)
    const size_t gemm2_smem = 3 * 3 * 16384;   // 144KB (fp16 2-term)
    static bool attr_set = false;
    if (!attr_set) {
        cudaFuncSetAttribute(lstm_persist,
                             cudaFuncAttributeMaxDynamicSharedMemorySize, (int)lstm_smem);
        cudaFuncSetAttribute(mma_gemm,
                             cudaFuncAttributeMaxDynamicSharedMemorySize, (int)gemm_smem);
        cudaFuncSetAttribute(mma_gemm_h2,
                             cudaFuncAttributeMaxDynamicSharedMemorySize, (int)gemm2_smem);
        attr_set = true;
    }

    // Zero output (invalid decoder rows stay zero after scattered projection)
    cudaMemsetAsync(out, 0, (size_t)out_size * sizeof(float), 0);
    cudaMemsetAsync(hbuf, 0, BSZ * HH * sizeof(float), 0);

    // Compact-row map from len_dec
    build_map<<<1, 128>>>(len_dec, map, nvalid);

    // Weight transposes: proj -> single fp16; Wx -> split bf16
    transpose_f16<<<dim3(VV / 32, DD / 32), 256>>>(proj_W, VV, Bt_h);
    transpose_split<<<dim3(G4 / 32, DD / 32), 256>>>(enc_W, G4, WeT_hi, WeT_lo);
    transpose_split<<<dim3(G4 / 32, DD / 32), 256>>>(dec_W, G4, WdT_hi, WdT_lo);

    // Embedding gathers + splits (bf16)
    gather_split<<<(TX * BSZ * DD) / 256, 256>>>(E, enc_ids, TX, Ae_hi, Ae_lo);
    gather_split<<<(TY * BSZ * DD) / 256, 256>>>(E, dec_ids, TY, Ad_hi, Ad_lo);

    // Pre-activations (3-term bf16, proven accuracy into the recurrence)
    mma_gemm<<<dim3(16, G4 / 128), 256, gemm_smem>>>(Ae_hi, Ae_lo, WeT_hi, WeT_lo,
                                                     enc_b, pre_enc, G4);
    mma_gemm<<<dim3(16, G4 / 128), 256, gemm_smem>>>(Ad_hi, Ad_lo, WdT_hi, WdT_lo,
                                                     dec_b, pre_dec, G4);

    // Full recurrence in one persistent kernel
    lstm_persist<<<NCTA, NTHR, lstm_smem>>>(
        pre_enc, pre_dec,
        enc_W + (size_t)DD * G4, dec_W + (size_t)DD * G4,
        len_enc, len_dec, hbuf, hs);

    // Compact + split hs (fp16), then 2-term fp16 projection over valid rows,
    // scattered through the row map (rest of out is zero).
    split_compact_f16<<<(BSZ * TY * DD) / 256, 256>>>(hs, map, Ah_hi, Ah_lo);
    mma_gemm_h2<<<dim3(16, VV / 128), 256, gemm2_smem>>>(Ah_hi, Ah_lo, Bt_h,
                                                         out, VV, map, nvalid);
}

// round 9
// speedup vs baseline: 3.1261x; 1.0820x over previous
#include <cuda_runtime.h>
#include <cuda_bf16.h>
#include <cuda_fp16.h>
#include <math.h>
#include <stdint.h>

// Problem constants
#define BSZ 32
#define TX  64
#define TY  64
#define DD  512
#define HH  512
#define G4  2048   // 4*H
#define VV  32000

#define NCTA 128   // persistent LSTM CTAs
#define NTHR 256

// ---------------- scratch (device globals; no allocation allowed) ----------------
__device__ float g_pre_enc[TX * BSZ * G4];
__device__ float g_pre_dec[TY * BSZ * G4];
__device__ float g_hbuf[2][BSZ * HH];
__device__ float g_hs[BSZ * TY * HH];
__device__ unsigned g_scnt[TX + TY];   // per-step arrival counters (zeroed each call)
__device__ int g_map[BSZ * TY];        // compact row -> original (b*64+t), -1 = pad
__device__ int g_nvalid;               // number of valid decoder rows

// bf16 3-term operands for the pre-activation GEMMs (K-major, K=512)
__device__ __nv_bfloat16 g_WeT_hi[G4 * DD], g_WeT_lo[G4 * DD];   // enc Wx^T  [4H][D]
__device__ __nv_bfloat16 g_WdT_hi[G4 * DD], g_WdT_lo[G4 * DD];   // dec Wx^T  [4H][D]
__device__ __nv_bfloat16 g_Ae_hi[TX * BSZ * DD], g_Ae_lo[TX * BSZ * DD];
__device__ __nv_bfloat16 g_Ad_hi[TY * BSZ * DD], g_Ad_lo[TY * BSZ * DD];

// fp16 2-term operands for the projection GEMM
__device__ __half g_Bt_h[VV * DD];                                // proj_W^T  [V][D], hi only
__device__ __half g_Ah_hi[BSZ * TY * DD], g_Ah_lo[BSZ * TY * DD]; // hs split fp16

// ======================= helpers =======================
__device__ __forceinline__ uint32_t smem_u32(const void* p) {
    uint32_t a;
    asm("{ .reg .u64 t; cvta.to.shared.u64 t, %1; cvt.u32.u64 %0, t; }" : "=r"(a) : "l"(p));
    return a;
}

#define LDSM4(r, addr) \
    asm volatile("ldmatrix.sync.aligned.m8n8.x4.shared.b16 {%0,%1,%2,%3}, [%4];" \
        : "=r"((r)[0]), "=r"((r)[1]), "=r"((r)[2]), "=r"((r)[3]) : "r"(addr))

#define MMA_BF16(d, a, b0, b1) \
    asm volatile("mma.sync.aligned.m16n8k16.row.col.f32.bf16.bf16.f32 " \
        "{%0,%1,%2,%3}, {%4,%5,%6,%7}, {%8,%9}, {%0,%1,%2,%3};" \
        : "+f"((d)[0]), "+f"((d)[1]), "+f"((d)[2]), "+f"((d)[3]) \
        : "r"((a)[0]), "r"((a)[1]), "r"((a)[2]), "r"((a)[3]), "r"(b0), "r"(b1))

#define MMA_F16(d, a, b0, b1) \
    asm volatile("mma.sync.aligned.m16n8k16.row.col.f32.f16.f16.f32 " \
        "{%0,%1,%2,%3}, {%4,%5,%6,%7}, {%8,%9}, {%0,%1,%2,%3};" \
        : "+f"((d)[0]), "+f"((d)[1]), "+f"((d)[2]), "+f"((d)[3]) \
        : "r"((a)[0]), "r"((a)[1]), "r"((a)[2]), "r"((a)[3]), "r"(b0), "r"(b1))

#define CP_ASYNC16(dst, src) \
    asm volatile("cp.async.cg.shared.global [%0], [%1], 16;" :: "r"(dst), "l"(src))
#define CP_COMMIT()  asm volatile("cp.async.commit_group;" ::: "memory")
#define CP_WAIT(n)   asm volatile("cp.async.wait_group %0;" :: "n"(n) : "memory")

// =====================================================================
// 3-term split-bf16 GEMM (pre-activations):
//   C[M,N] = (Ahi+Alo)[M,512] @ (Bhi+Blo)[N,512]^T + bias
// CTA 128x128, BK=64, 3-stage cp.async pipeline (3 x 64KB smem).
// =====================================================================
__global__ __launch_bounds__(256, 1)
void mma_gemm(const __nv_bfloat16* __restrict__ Ahi, const __nv_bfloat16* __restrict__ Alo,
              const __nv_bfloat16* __restrict__ Bhi, const __nv_bfloat16* __restrict__ Blo,
              const float* __restrict__ bias, float* __restrict__ C, int N)
{
    extern __shared__ char smc[];
    const uint32_t sbase = smem_u32(smc);

    const int tid  = threadIdx.x;
    const int wid  = tid >> 5;
    const int lane = tid & 31;
    const int m0 = blockIdx.x * 128;
    const int n0 = blockIdx.y * 128;
    const int wm = (wid & 3) * 32;
    const int wn = (wid >> 2) * 64;

    const __nv_bfloat16* srcs[4] = { Ahi, Alo, Bhi, Blo };
    const int rb[4] = { m0, m0, n0, n0 };

    uint32_t dsts[4];
    const __nv_bfloat16* gsrc[4][4];
#pragma unroll
    for (int q = 0; q < 4; q++) {
        const int i = tid + q * 256;
        const int r = i >> 3, u = i & 7;
        dsts[q] = (uint32_t)(r * 128 + ((u ^ (r & 7)) << 4));
#pragma unroll
        for (int t4 = 0; t4 < 4; t4++)
            gsrc[t4][q] = srcs[t4] + (size_t)(rb[t4] + r) * DD + u * 8;
    }

    float acc[2][8][4];
#pragma unroll
    for (int mt = 0; mt < 2; mt++)
#pragma unroll
        for (int nt = 0; nt < 8; nt++)
#pragma unroll
            for (int e = 0; e < 4; e++) acc[mt][nt][e] = 0.f;

#pragma unroll
    for (int s = 0; s < 2; s++) {
        const uint32_t sb = sbase + (uint32_t)s * 65536u;
        const int koff = s * 64;
#pragma unroll
        for (int t4 = 0; t4 < 4; t4++)
#pragma unroll
            for (int q = 0; q < 4; q++)
                CP_ASYNC16(sb + t4 * 16384 + dsts[q], gsrc[t4][q] + koff);
        CP_COMMIT();
    }

    const int lrow15 = lane & 15;
    const int lhalf  = lane >> 4;

    int cs = 0;
    for (int it = 0; it < 8; it++) {
        if (it < 7) { CP_WAIT(1); } else { CP_WAIT(0); }
        __syncthreads();

        if (it + 2 < 8) {
            int ps = cs + 2; if (ps >= 3) ps -= 3;
            const uint32_t sb = sbase + (uint32_t)ps * 65536u;
            const int koff = (it + 2) * 64;
#pragma unroll
            for (int t4 = 0; t4 < 4; t4++)
#pragma unroll
                for (int q = 0; q < 4; q++)
                    CP_ASYNC16(sb + t4 * 16384 + dsts[q], gsrc[t4][q] + koff);
            CP_COMMIT();
        }

        const uint32_t B = sbase + (uint32_t)cs * 65536u;

#pragma unroll
        for (int j = 0; j < 4; j++) {
            uint32_t ah[2][4], al[2][4];
            uint32_t bh[4][4], bl[4][4];
#pragma unroll
            for (int mt = 0; mt < 2; mt++) {
                const int row = wm + mt * 16 + lrow15;
                const int unit = j * 2 + lhalf;
                const uint32_t addr = B + row * 128 + (((unit ^ (row & 7))) << 4);
                LDSM4(ah[mt], addr);
                LDSM4(al[mt], addr + 16384);
            }
#pragma unroll
            for (int g = 0; g < 4; g++) {
                const int row = wn + g * 16 + lrow15;
                const int unit = j * 2 + lhalf;
                const uint32_t addr = B + 32768 + row * 128 + (((unit ^ (row & 7))) << 4);
                LDSM4(bh[g], addr);
                LDSM4(bl[g], addr + 16384);
            }
#pragma unroll
            for (int mt = 0; mt < 2; mt++)
#pragma unroll
                for (int nt = 0; nt < 8; nt++) {
                    const int g = nt >> 1, o = nt & 1;
                    MMA_BF16(acc[mt][nt], ah[mt], bh[g][o], bh[g][o + 2]);
                    MMA_BF16(acc[mt][nt], ah[mt], bl[g][o], bl[g][o + 2]);
                    MMA_BF16(acc[mt][nt], al[mt], bh[g][o], bh[g][o + 2]);
                }
        }
        cs++; if (cs == 3) cs = 0;
    }

    const int erow = wm + (lane >> 2);
    const int ec = n0 + wn + (lane & 3) * 2;
#pragma unroll
    for (int mt = 0; mt < 2; mt++) {
        const int r0 = m0 + erow + mt * 16;
#pragma unroll
        for (int nt = 0; nt < 8; nt++) {
            const int col = ec + nt * 8;
            float b0 = 0.f, b1 = 0.f;
            if (bias) { b0 = bias[col]; b1 = bias[col + 1]; }
            float* p0 = C + (size_t)r0 * N + col;
            float* p1 = C + (size_t)(r0 + 8) * N + col;
            p0[0] = acc[mt][nt][0] + b0;
            p0[1] = acc[mt][nt][1] + b1;
            p1[0] = acc[mt][nt][2] + b0;
            p1[1] = acc[mt][nt][3] + b1;
        }
    }
}

// =====================================================================
// 2-term split-fp16 GEMM (projection):
//   C[M,N] = (Ahi+Alo)_fp16[M,512] @ Bh_fp16[N,512]^T
// 3 operand tiles (48KB/stage), 3-stage pipeline. A rows compacted.
// =====================================================================
__global__ __launch_bounds__(256, 1)
void mma_gemm_h2(const __half* __restrict__ Ahi, const __half* __restrict__ Alo,
                 const __half* __restrict__ Bh,
                 float* __restrict__ C, int N,
                 const int* __restrict__ map, const int* __restrict__ nvalidp)
{
    const int m0 = blockIdx.x * 128;
    const int n0 = blockIdx.y * 128;
    if (m0 >= *nvalidp) return;

    extern __shared__ char smc[];
    const uint32_t sbase = smem_u32(smc);

    const int tid  = threadIdx.x;
    const int wid  = tid >> 5;
    const int lane = tid & 31;
    const int wm = (wid & 3) * 32;
    const int wn = (wid >> 2) * 64;

    const __half* srcs[3] = { Ahi, Alo, Bh };
    const int rb[3] = { m0, m0, n0 };

    uint32_t dsts[4];
    const __half* gsrc[3][4];
#pragma unroll
    for (int q = 0; q < 4; q++) {
        const int i = tid + q * 256;
        const int r = i >> 3, u = i & 7;
        dsts[q] = (uint32_t)(r * 128 + ((u ^ (r & 7)) << 4));
#pragma unroll
        for (int t3 = 0; t3 < 3; t3++)
            gsrc[t3][q] = srcs[t3] + (size_t)(rb[t3] + r) * DD + u * 8;
    }

    float acc[2][8][4];
#pragma unroll
    for (int mt = 0; mt < 2; mt++)
#pragma unroll
        for (int nt = 0; nt < 8; nt++)
#pragma unroll
            for (int e = 0; e < 4; e++) acc[mt][nt][e] = 0.f;

#pragma unroll
    for (int s = 0; s < 2; s++) {
        const uint32_t sb = sbase + (uint32_t)s * 49152u;
        const int koff = s * 64;
#pragma unroll
        for (int t3 = 0; t3 < 3; t3++)
#pragma unroll
            for (int q = 0; q < 4; q++)
                CP_ASYNC16(sb + t3 * 16384 + dsts[q], gsrc[t3][q] + koff);
        CP_COMMIT();
    }

    const int lrow15 = lane & 15;
    const int lhalf  = lane >> 4;

    int cs = 0;
    for (int it = 0; it < 8; it++) {
        if (it < 7) { CP_WAIT(1); } else { CP_WAIT(0); }
        __syncthreads();

        if (it + 2 < 8) {
            int ps = cs + 2; if (ps >= 3) ps -= 3;
            const uint32_t sb = sbase + (uint32_t)ps * 49152u;
            const int koff = (it + 2) * 64;
#pragma unroll
            for (int t3 = 0; t3 < 3; t3++)
#pragma unroll
                for (int q = 0; q < 4; q++)
                    CP_ASYNC16(sb + t3 * 16384 + dsts[q], gsrc[t3][q] + koff);
            CP_COMMIT();
        }

        const uint32_t B = sbase + (uint32_t)cs * 49152u;

#pragma unroll
        for (int j = 0; j < 4; j++) {
            uint32_t ah[2][4], al[2][4];
            uint32_t bh[4][4];
#pragma unroll
            for (int mt = 0; mt < 2; mt++) {
                const int row = wm + mt * 16 + lrow15;
                const int unit = j * 2 + lhalf;
                const uint32_t addr = B + row * 128 + (((unit ^ (row & 7))) << 4);
                LDSM4(ah[mt], addr);
                LDSM4(al[mt], addr + 16384);
            }
#pragma unroll
            for (int g = 0; g < 4; g++) {
                const int row = wn + g * 16 + lrow15;
                const int unit = j * 2 + lhalf;
                const uint32_t addr = B + 32768 + row * 128 + (((unit ^ (row & 7))) << 4);
                LDSM4(bh[g], addr);
            }
#pragma unroll
            for (int mt = 0; mt < 2; mt++)
#pragma unroll
                for (int nt = 0; nt < 8; nt++) {
                    const int g = nt >> 1, o = nt & 1;
                    MMA_F16(acc[mt][nt], ah[mt], bh[g][o], bh[g][o + 2]);
                    MMA_F16(acc[mt][nt], al[mt], bh[g][o], bh[g][o + 2]);
                }
        }
        cs++; if (cs == 3) cs = 0;
    }

    const int erow = wm + (lane >> 2);
    const int ec = n0 + wn + (lane & 3) * 2;
#pragma unroll
    for (int mt = 0; mt < 2; mt++) {
        const int r0 = m0 + erow + mt * 16;
        const int r1 = r0 + 8;
        const int o0 = map[r0];
        const int o1 = map[r1];
#pragma unroll
        for (int nt = 0; nt < 8; nt++) {
            const int col = ec + nt * 8;
            if (o0 >= 0) {
                float* p0 = C + (size_t)o0 * N + col;
                p0[0] = acc[mt][nt][0];
                p0[1] = acc[mt][nt][1];
            }
            if (o1 >= 0) {
                float* p1 = C + (size_t)o1 * N + col;
                p1[0] = acc[mt][nt][2];
                p1[1] = acc[mt][nt][3];
            }
        }
    }
}

// =====================================================================
// Build compact row map from len_dec.
// =====================================================================
__global__ void build_map(const int* __restrict__ len_dec,
                          int* __restrict__ map, int* __restrict__ nvalid)
{
    __shared__ int off[BSZ];
    const int tid = threadIdx.x;
    if (tid == 0) {
        int acc = 0;
        for (int b = 0; b < BSZ; b++) {
            off[b] = acc;
            int L = len_dec[b];
            if (L < 0) L = 0;
            if (L > TY) L = TY;
            acc += L;
        }
        *nvalid = acc;
    }
    __syncthreads();
    for (int i = tid; i < BSZ * TY; i += blockDim.x) map[i] = -1;
    __syncthreads();
    for (int b = 0; b < BSZ; b++) {
        int L = len_dec[b];
        if (L > TY) L = TY;
        for (int t = tid; t < L; t += blockDim.x)
            map[off[b] + t] = b * TY + t;
    }
}

// Compact + split hs into fp16 hi/lo.
__global__ void split_compact_f16(const float* __restrict__ src,
                                  const int* __restrict__ map,
                                  __half* __restrict__ hi, __half* __restrict__ lo)
{
    const int i = blockIdx.x * 256 + threadIdx.x;
    const int j = i >> 9, k = i & 511;
    const int s = map[j];
    const float v = (s >= 0) ? src[(size_t)s * DD + k] : 0.f;
    const __half h = __float2half(v);
    hi[i] = h;
    lo[i] = __float2half(v - __half2float(h));
}

// Transpose + single fp16:  src[K=512][N] f32  ->  h [N][512] fp16
__global__ void transpose_f16(const float* __restrict__ src, int N,
                              __half* __restrict__ dst)
{
    __shared__ float t[32][33];
    const int tx = threadIdx.x & 31, ty = threadIdx.x >> 5;
    const int n = blockIdx.x * 32 + tx;
    const int kb = blockIdx.y * 32;
#pragma unroll
    for (int r = 0; r < 32; r += 8)
        t[ty + r][tx] = src[(size_t)(kb + ty + r) * N + n];
    __syncthreads();
#pragma unroll
    for (int r = 0; r < 32; r += 8) {
        const int nn = blockIdx.x * 32 + ty + r;
        const int kk = kb + tx;
        dst[(size_t)nn * DD + kk] = __float2half(t[tx][ty + r]);
    }
}

// Transpose + split bf16:  src[K=512][N] f32  ->  hi/lo [N][512] bf16
__global__ void transpose_split(const float* __restrict__ src, int N,
                                __nv_bfloat16* __restrict__ hi, __nv_bfloat16* __restrict__ lo)
{
    __shared__ float t[32][33];
    const int tx = threadIdx.x & 31, ty = threadIdx.x >> 5;
    const int n = blockIdx.x * 32 + tx;
    const int kb = blockIdx.y * 32;
#pragma unroll
    for (int r = 0; r < 32; r += 8)
        t[ty + r][tx] = src[(size_t)(kb + ty + r) * N + n];
    __syncthreads();
#pragma unroll
    for (int r = 0; r < 32; r += 8) {
        const int nn = blockIdx.x * 32 + ty + r;
        const int kk = kb + tx;
        const float v = t[tx][ty + r];
        const __nv_bfloat16 h = __float2bfloat16(v);
        hi[(size_t)nn * DD + kk] = h;
        lo[(size_t)nn * DD + kk] = __float2bfloat16(v - __bfloat162float(h));
    }
}

// Embedding gather + split bf16
__global__ void gather_split(const float* __restrict__ E, const int* __restrict__ ids, int idxT,
                             __nv_bfloat16* __restrict__ hi, __nv_bfloat16* __restrict__ lo)
{
    const int i = blockIdx.x * 256 + threadIdx.x;
    const int row = i >> 9, k = i & 511;
    const int b = row & 31, t = row >> 5;
    const float v = E[(size_t)ids[b * idxT + t] * DD + k];
    const __nv_bfloat16 h = __float2bfloat16(v);
    hi[i] = h;
    lo[i] = __float2bfloat16(v - __bfloat162float(h));
}

// =====================================================================
// Persistent LSTM: all 128 timesteps, one launch.
// Step sync: per-step arrival counter + scoped release/acquire atomics
// (no GPU-scope membar on the critical path).
// =====================================================================
__global__ __launch_bounds__(NTHR, 1)
void lstm_persist(const float* __restrict__ pre_enc, const float* __restrict__ pre_dec,
                  const float* __restrict__ enc_Wh, const float* __restrict__ dec_Wh,
                  const int* __restrict__ len_enc, const int* __restrict__ len_dec,
                  float* __restrict__ hbuf, float* __restrict__ hs,
                  unsigned* __restrict__ scnt)
{
    extern __shared__ float smf[];
    float* whs  = smf;                    // 16*520
    float* hsm  = smf + 16 * 520;         // 32*516
    float* zbuf = hsm + 32 * 516;         // 32*17

    const int tid = threadIdx.x;
    const int cta = blockIdx.x;
    const int zc  = tid & 15;
    const int bb  = tid >> 4;
    const int b0  = bb * 2, b1 = bb * 2 + 1;

    // gate-phase constants (tid < 128)
    const int gb  = tid >> 2;        // b
    const int ghc = tid & 3;         // hc
    const int gn  = cta * 4 + ghc;   // h column

    float c_reg = 0.f;

    for (int phase = 0; phase < 2; phase++) {
        const float* Wh  = phase ? dec_Wh  : enc_Wh;
        const float* pre = phase ? pre_dec : pre_enc;
        const int*   len = phase ? len_dec : len_enc;

        for (int i = tid; i < 16 * 512; i += NTHR) {
            int z = i >> 9, k = i & 511;
            whs[z * 520 + k] =
                __ldg(&Wh[(size_t)k * G4 + (z >> 2) * 512 + cta * 4 + (z & 3)]);
        }
        const int mylen = (tid < 128) ? len[gb] : 0;
        __syncthreads();

        for (int s = 0; s < 64; s++) {
            const int sigma = phase * 64 + s;
            const float* hin  = hbuf + (sigma & 1) * (BSZ * HH);
            float*       hout = hbuf + ((sigma + 1) & 1) * (BSZ * HH);

            // Prefetch this step's pre-activations (consumed after the dot).
            float pzi = 0.f, pzj = 0.f, pzf = 0.f, pzo = 0.f;
            if (tid < 128) {
                const float* pz = pre + (size_t)s * BSZ * G4 + (size_t)gb * G4 + gn;
                pzi = __ldg(pz);
                pzj = __ldg(pz + 512);
                pzf = __ldg(pz + 1024);
                pzo = __ldg(pz + 1536);
            }

            // Stage h into smem (L2-coherent loads; L1 may be stale across SMs).
            for (int i = tid; i < (BSZ * HH) / 4; i += NTHR) {
                int b = i >> 7, k4 = i & 127;
                float4 v = __ldcg((const float4*)&hin[b * HH + k4 * 4]);
                *(float4*)&hsm[b * 516 + k4 * 4] = v;
            }
            __syncthreads();

            float acc0 = 0.f, acc1 = 0.f;
            const float* wr  = &whs[zc * 520];
            const float* h0r = &hsm[b0 * 516];
            const float* h1r = &hsm[b1 * 516];
#pragma unroll 4
            for (int k = 0; k < 512; k += 4) {
                float4 w4 = *(const float4*)&wr[k];
                float4 ha = *(const float4*)&h0r[k];
                float4 hb = *(const float4*)&h1r[k];
                acc0 += ha.x * w4.x + ha.y * w4.y + ha.z * w4.z + ha.w * w4.w;
                acc1 += hb.x * w4.x + hb.y * w4.y + hb.z * w4.z + hb.w * w4.w;
            }
            zbuf[b0 * 17 + zc] = acc0;
            zbuf[b1 * 17 + zc] = acc1;
            __syncthreads();

            if (tid < 128) {
                float zi = pzi + zbuf[gb * 17 + ghc];
                float zj = pzj + zbuf[gb * 17 + 4 + ghc];
                float zf = pzf + zbuf[gb * 17 + 8 + ghc];
                float zo = pzo + zbuf[gb * 17 + 12 + ghc];

                float fg = 1.f / (1.f + expf(-(zf + 1.0f)));   // forget bias 1.0
                float ig = 1.f / (1.f + expf(-zi));
                float og = 1.f / (1.f + expf(-zo));
                float cn = c_reg * fg + ig * tanhf(zj);
                float hn = tanhf(cn) * og;

                bool m = (s < mylen);
                float hprev = hsm[gb * 516 + gn];
                c_reg = m ? cn : c_reg;
                hout[gb * HH + gn] = m ? hn : hprev;
                if (phase)
                    hs[((size_t)gb * TY + s) * HH + gn] = m ? hn : 0.f;
            }
            __syncthreads();   // all h stores issued before arrival

            if (tid == 0) {
                unsigned* ctr = scnt + sigma;
                // release: publish this CTA's h stores at GPU scope
                asm volatile("red.release.gpu.global.add.u32 [%0], 1;"
                             :: "l"(ctr) : "memory");
                unsigned v;
                do {
                    asm volatile("ld.acquire.gpu.global.u32 %0, [%1];"
                                 : "=r"(v) : "l"(ctr) : "memory");
                } while (v < NCTA);
            }
            __syncthreads();   // propagate tid0's acquire to the CTA
        }
    }
}

// =====================================================================
// Host launcher (graph-capturable)
// =====================================================================
extern "C" void kernel_launch(void* const* d_in, const int* in_sizes, int n_in,
                              void* d_out, int out_size)
{
    const int*   enc_ids = (const int*)d_in[0];
    const int*   dec_ids = (const int*)d_in[1];
    const int*   len_enc = (const int*)d_in[2];
    const int*   len_dec = (const int*)d_in[3];
    const float* E       = (const float*)d_in[4];
    const float* enc_W   = (const float*)d_in[5];
    const float* enc_b   = (const float*)d_in[6];
    const float* dec_W   = (const float*)d_in[7];
    const float* dec_b   = (const float*)d_in[8];
    const float* proj_W  = (const float*)d_in[9];
    float*       out     = (float*)d_out;

    float *pre_enc, *pre_dec, *hbuf, *hs;
    unsigned* scnt;
    int *map, *nvalid;
    cudaGetSymbolAddress((void**)&pre_enc, g_pre_enc);
    cudaGetSymbolAddress((void**)&pre_dec, g_pre_dec);
    cudaGetSymbolAddress((void**)&hbuf,    g_hbuf);
    cudaGetSymbolAddress((void**)&hs,      g_hs);
    cudaGetSymbolAddress((void**)&scnt,    g_scnt);
    cudaGetSymbolAddress((void**)&map,     g_map);
    cudaGetSymbolAddress((void**)&nvalid,  g_nvalid);

    __nv_bfloat16 *WeT_hi, *WeT_lo, *WdT_hi, *WdT_lo;
    __nv_bfloat16 *Ae_hi, *Ae_lo, *Ad_hi, *Ad_lo;
    __half *Bt_h, *Ah_hi, *Ah_lo;
    cudaGetSymbolAddress((void**)&WeT_hi, g_WeT_hi);
    cudaGetSymbolAddress((void**)&WeT_lo, g_WeT_lo);
    cudaGetSymbolAddress((void**)&WdT_hi, g_WdT_hi);
    cudaGetSymbolAddress((void**)&WdT_lo, g_WdT_lo);
    cudaGetSymbolAddress((void**)&Ae_hi,  g_Ae_hi);
    cudaGetSymbolAddress((void**)&Ae_lo,  g_Ae_lo);
    cudaGetSymbolAddress((void**)&Ad_hi,  g_Ad_hi);
    cudaGetSymbolAddress((void**)&Ad_lo,  g_Ad_lo);
    cudaGetSymbolAddress((void**)&Bt_h,   g_Bt_h);
    cudaGetSymbolAddress((void**)&Ah_hi,  g_Ah_hi);
    cudaGetSymbolAddress((void**)&Ah_lo,  g_Ah_lo);

    const size_t lstm_smem  = (16 * 520 + 32 * 516 + 32 * 17) * sizeof(float);
    const size_t gemm_smem  = 3 * 4 * 16384;   // 192KB (bf16 3-term)
    const size_t gemm2_smem = 3 * 3 * 16384;   // 144KB (fp16 2-term)
    static bool attr_set = false;
    if (!attr_set) {
        cudaFuncSetAttribute(lstm_persist,
                             cudaFuncAttributeMaxDynamicSharedMemorySize, (int)lstm_smem);
        cudaFuncSetAttribute(mma_gemm,
                             cudaFuncAttributeMaxDynamicSharedMemorySize, (int)gemm_smem);
        cudaFuncSetAttribute(mma_gemm_h2,
                             cudaFuncAttributeMaxDynamicSharedMemorySize, (int)gemm2_smem);
        attr_set = true;
    }

    // Zero output, initial h, and per-step barrier counters.
    cudaMemsetAsync(out, 0, (size_t)out_size * sizeof(float), 0);
    cudaMemsetAsync(hbuf, 0, BSZ * HH * sizeof(float), 0);
    cudaMemsetAsync(scnt, 0, (TX + TY) * sizeof(unsigned), 0);

    // Compact-row map from len_dec
    build_map<<<1, 128>>>(len_dec, map, nvalid);

    // Weight transposes: proj -> single fp16; Wx -> split bf16
    transpose_f16<<<dim3(VV / 32, DD / 32), 256>>>(proj_W, VV, Bt_h);
    transpose_split<<<dim3(G4 / 32, DD / 32), 256>>>(enc_W, G4, WeT_hi, WeT_lo);
    transpose_split<<<dim3(G4 / 32, DD / 32), 256>>>(dec_W, G4, WdT_hi, WdT_lo);

    // Embedding gathers + splits (bf16)
    gather_split<<<(TX * BSZ * DD) / 256, 256>>>(E, enc_ids, TX, Ae_hi, Ae_lo);
    gather_split<<<(TY * BSZ * DD) / 256, 256>>>(E, dec_ids, TY, Ad_hi, Ad_lo);

    // Pre-activations (3-term bf16)
    mma_gemm<<<dim3(16, G4 / 128), 256, gemm_smem>>>(Ae_hi, Ae_lo, WeT_hi, WeT_lo,
                                                     enc_b, pre_enc, G4);
    mma_gemm<<<dim3(16, G4 / 128), 256, gemm_smem>>>(Ad_hi, Ad_lo, WdT_hi, WdT_lo,
                                                     dec_b, pre_dec, G4);

    // Full recurrence in one persistent kernel
    lstm_persist<<<NCTA, NTHR, lstm_smem>>>(
        pre_enc, pre_dec,
        enc_W + (size_t)DD * G4, dec_W + (size_t)DD * G4,
        len_enc, len_dec, hbuf, hs, scnt);

    // Compact + split hs (fp16), then 2-term fp16 projection over valid rows.
    split_compact_f16<<<(BSZ * TY * DD) / 256, 256>>>(hs, map, Ah_hi, Ah_lo);
    mma_gemm_h2<<<dim3(16, VV / 128), 256, gemm2_smem>>>(Ah_hi, Ah_lo, Bt_h,
                                                         out, VV, map, nvalid);
}

// round 10
// speedup vs baseline: 3.4307x; 1.0974x over previous
#include <cuda_runtime.h>
#include <cuda_bf16.h>
#include <cuda_fp16.h>
#include <math.h>
#include <stdint.h>

// Problem constants
#define BSZ 32
#define TX  64
#define TY  64
#define DD  512
#define HH  512
#define G4  2048   // 4*H
#define VV  32000

#define NCTA 128   // persistent LSTM CTAs
#define NTHR 256

// ---------------- scratch (device globals; no allocation allowed) ----------------
__device__ float g_pre_enc[TX * BSZ * G4];
__device__ float g_pre_dec[TY * BSZ * G4];
__device__ float g_hbuf[2][BSZ * HH];
__device__ float g_hs[BSZ * TY * HH];
__device__ unsigned g_scnt[TX + TY];   // per-step arrival counters (zeroed each call)
__device__ int g_map[BSZ * TY];        // compact row -> original (b*64+t), -1 = pad
__device__ int g_nvalid;               // number of valid decoder rows

// bf16 3-term operands for the pre-activation GEMMs (K-major, K=512)
__device__ __nv_bfloat16 g_WeT_hi[G4 * DD], g_WeT_lo[G4 * DD];   // enc Wx^T  [4H][D]
__device__ __nv_bfloat16 g_WdT_hi[G4 * DD], g_WdT_lo[G4 * DD];   // dec Wx^T  [4H][D]
__device__ __nv_bfloat16 g_Ae_hi[TX * BSZ * DD], g_Ae_lo[TX * BSZ * DD];
__device__ __nv_bfloat16 g_Ad_hi[TY * BSZ * DD], g_Ad_lo[TY * BSZ * DD];

// fp16 2-term operands for the projection GEMM
__device__ __half g_Bt_h[VV * DD];                                // proj_W^T  [V][D], hi only
__device__ __half g_Ah_hi[BSZ * TY * DD], g_Ah_lo[BSZ * TY * DD]; // hs split fp16

// ======================= helpers =======================
__device__ __forceinline__ uint32_t smem_u32(const void* p) {
    uint32_t a;
    asm("{ .reg .u64 t; cvta.to.shared.u64 t, %1; cvt.u32.u64 %0, t; }" : "=r"(a) : "l"(p));
    return a;
}

#define LDSM4(r, addr) \
    asm volatile("ldmatrix.sync.aligned.m8n8.x4.shared.b16 {%0,%1,%2,%3}, [%4];" \
        : "=r"((r)[0]), "=r"((r)[1]), "=r"((r)[2]), "=r"((r)[3]) : "r"(addr))

#define MMA_BF16(d, a, b0, b1) \
    asm volatile("mma.sync.aligned.m16n8k16.row.col.f32.bf16.bf16.f32 " \
        "{%0,%1,%2,%3}, {%4,%5,%6,%7}, {%8,%9}, {%0,%1,%2,%3};" \
        : "+f"((d)[0]), "+f"((d)[1]), "+f"((d)[2]), "+f"((d)[3]) \
        : "r"((a)[0]), "r"((a)[1]), "r"((a)[2]), "r"((a)[3]), "r"(b0), "r"(b1))

#define MMA_F16(d, a, b0, b1) \
    asm volatile("mma.sync.aligned.m16n8k16.row.col.f32.f16.f16.f32 " \
        "{%0,%1,%2,%3}, {%4,%5,%6,%7}, {%8,%9}, {%0,%1,%2,%3};" \
        : "+f"((d)[0]), "+f"((d)[1]), "+f"((d)[2]), "+f"((d)[3]) \
        : "r"((a)[0]), "r"((a)[1]), "r"((a)[2]), "r"((a)[3]), "r"(b0), "r"(b1))

#define CP_ASYNC16(dst, src) \
    asm volatile("cp.async.cg.shared.global [%0], [%1], 16;" :: "r"(dst), "l"(src))
#define CP_COMMIT()  asm volatile("cp.async.commit_group;" ::: "memory")
#define CP_WAIT(n)   asm volatile("cp.async.wait_group %0;" :: "n"(n) : "memory")

// packed f32x2 FMA (Blackwell base ISA): d = a*b + d  elementwise on 2 floats
__device__ __forceinline__ void fma2(uint64_t& d, uint64_t a, uint64_t b) {
    asm("fma.rn.f32x2 %0, %1, %2, %0;" : "+l"(d) : "l"(a), "l"(b));
}
__device__ __forceinline__ float pairsum(uint64_t v) {
    return __uint_as_float((uint32_t)v) + __uint_as_float((uint32_t)(v >> 32));
}

// =====================================================================
// Fused zero-init: h state buffer 0 + per-step barrier counters.
// =====================================================================
__global__ void zero_misc(float* __restrict__ hbuf, unsigned* __restrict__ scnt)
{
    const int i = blockIdx.x * 256 + threadIdx.x;
    if (i < BSZ * HH) hbuf[i] = 0.f;
    if (i < TX + TY)  scnt[i] = 0u;
}

// =====================================================================
// Build compact row map from len_dec.
// =====================================================================
__global__ void build_map(const int* __restrict__ len_dec,
                          int* __restrict__ map, int* __restrict__ nvalid)
{
    __shared__ int off[BSZ];
    const int tid = threadIdx.x;
    if (tid == 0) {
        int acc = 0;
        for (int b = 0; b < BSZ; b++) {
            off[b] = acc;
            int L = len_dec[b];
            if (L < 0) L = 0;
            if (L > TY) L = TY;
            acc += L;
        }
        *nvalid = acc;
    }
    __syncthreads();
    for (int i = tid; i < BSZ * TY; i += blockDim.x) map[i] = -1;
    __syncthreads();
    for (int b = 0; b < BSZ; b++) {
        int L = len_dec[b];
        if (L > TY) L = TY;
        for (int t = tid; t < L; t += blockDim.x)
            map[off[b] + t] = b * TY + t;
    }
}

// =====================================================================
// Fused transpose + split bf16 for BOTH Wx weights (z = 0 enc, 1 dec):
//   src[K=512][G4] f32  ->  hi/lo [G4][512] bf16
// =====================================================================
__global__ void transpose_both(const float* __restrict__ srcE, const float* __restrict__ srcD,
                               __nv_bfloat16* __restrict__ hiE, __nv_bfloat16* __restrict__ loE,
                               __nv_bfloat16* __restrict__ hiD, __nv_bfloat16* __restrict__ loD)
{
    const float* src = blockIdx.z ? srcD : srcE;
    __nv_bfloat16* hi = blockIdx.z ? hiD : hiE;
    __nv_bfloat16* lo = blockIdx.z ? loD : loE;

    __shared__ float t[32][33];
    const int tx = threadIdx.x & 31, ty = threadIdx.x >> 5;
    const int n = blockIdx.x * 32 + tx;
    const int kb = blockIdx.y * 32;
#pragma unroll
    for (int r = 0; r < 32; r += 8)
        t[ty + r][tx] = src[(size_t)(kb + ty + r) * G4 + n];
    __syncthreads();
#pragma unroll
    for (int r = 0; r < 32; r += 8) {
        const int nn = blockIdx.x * 32 + ty + r;
        const int kk = kb + tx;
        const float v = t[tx][ty + r];
        const __nv_bfloat16 h = __float2bfloat16(v);
        hi[(size_t)nn * DD + kk] = h;
        lo[(size_t)nn * DD + kk] = __float2bfloat16(v - __bfloat162float(h));
    }
}

// =====================================================================
// Fused embedding gather + split bf16 for BOTH sequences (y = 0 enc, 1 dec)
// =====================================================================
__global__ void gather_both(const float* __restrict__ E,
                            const int* __restrict__ idsE, const int* __restrict__ idsD,
                            __nv_bfloat16* __restrict__ hiE, __nv_bfloat16* __restrict__ loE,
                            __nv_bfloat16* __restrict__ hiD, __nv_bfloat16* __restrict__ loD)
{
    const int* ids = blockIdx.y ? idsD : idsE;
    __nv_bfloat16* hi = blockIdx.y ? hiD : hiE;
    __nv_bfloat16* lo = blockIdx.y ? loD : loE;
    const int idxT = blockIdx.y ? TY : TX;

    const int i = blockIdx.x * 256 + threadIdx.x;
    const int row = i >> 9, k = i & 511;
    const int b = row & 31, t = row >> 5;
    const float v = E[(size_t)ids[b * idxT + t] * DD + k];
    const __nv_bfloat16 h = __float2bfloat16(v);
    hi[i] = h;
    lo[i] = __float2bfloat16(v - __bfloat162float(h));
}

// =====================================================================
// Fused 3-term split-bf16 GEMM for BOTH pre-activations (z = 0 enc, 1 dec):
//   C[2048, G4] = (Ahi+Alo) @ (Bhi+Blo)^T + bias
// CTA 128x128, BK=64, 3-stage cp.async pipeline (3 x 64KB smem).
// =====================================================================
__global__ __launch_bounds__(256, 1)
void mma_gemm_pre(const __nv_bfloat16* __restrict__ AhiE, const __nv_bfloat16* __restrict__ AloE,
                  const __nv_bfloat16* __restrict__ BhiE, const __nv_bfloat16* __restrict__ BloE,
                  const float* __restrict__ biasE, float* __restrict__ CE,
                  const __nv_bfloat16* __restrict__ AhiD, const __nv_bfloat16* __restrict__ AloD,
                  const __nv_bfloat16* __restrict__ BhiD, const __nv_bfloat16* __restrict__ BloD,
                  const float* __restrict__ biasD, float* __restrict__ CD)
{
    const __nv_bfloat16* Ahi = blockIdx.z ? AhiD : AhiE;
    const __nv_bfloat16* Alo = blockIdx.z ? AloD : AloE;
    const __nv_bfloat16* Bhi = blockIdx.z ? BhiD : BhiE;
    const __nv_bfloat16* Blo = blockIdx.z ? BloD : BloE;
    const float* bias = blockIdx.z ? biasD : biasE;
    float* C = blockIdx.z ? CD : CE;
    const int N = G4;

    extern __shared__ char smc[];
    const uint32_t sbase = smem_u32(smc);

    const int tid  = threadIdx.x;
    const int wid  = tid >> 5;
    const int lane = tid & 31;
    const int m0 = blockIdx.x * 128;
    const int n0 = blockIdx.y * 128;
    const int wm = (wid & 3) * 32;
    const int wn = (wid >> 2) * 64;

    const __nv_bfloat16* srcs[4] = { Ahi, Alo, Bhi, Blo };
    const int rb[4] = { m0, m0, n0, n0 };

    uint32_t dsts[4];
    const __nv_bfloat16* gsrc[4][4];
#pragma unroll
    for (int q = 0; q < 4; q++) {
        const int i = tid + q * 256;
        const int r = i >> 3, u = i & 7;
        dsts[q] = (uint32_t)(r * 128 + ((u ^ (r & 7)) << 4));
#pragma unroll
        for (int t4 = 0; t4 < 4; t4++)
            gsrc[t4][q] = srcs[t4] + (size_t)(rb[t4] + r) * DD + u * 8;
    }

    float acc[2][8][4];
#pragma unroll
    for (int mt = 0; mt < 2; mt++)
#pragma unroll
        for (int nt = 0; nt < 8; nt++)
#pragma unroll
            for (int e = 0; e < 4; e++) acc[mt][nt][e] = 0.f;

#pragma unroll
    for (int s = 0; s < 2; s++) {
        const uint32_t sb = sbase + (uint32_t)s * 65536u;
        const int koff = s * 64;
#pragma unroll
        for (int t4 = 0; t4 < 4; t4++)
#pragma unroll
            for (int q = 0; q < 4; q++)
                CP_ASYNC16(sb + t4 * 16384 + dsts[q], gsrc[t4][q] + koff);
        CP_COMMIT();
    }

    const int lrow15 = lane & 15;
    const int lhalf  = lane >> 4;

    int cs = 0;
    for (int it = 0; it < 8; it++) {
        if (it < 7) { CP_WAIT(1); } else { CP_WAIT(0); }
        __syncthreads();

        if (it + 2 < 8) {
            int ps = cs + 2; if (ps >= 3) ps -= 3;
            const uint32_t sb = sbase + (uint32_t)ps * 65536u;
            const int koff = (it + 2) * 64;
#pragma unroll
            for (int t4 = 0; t4 < 4; t4++)
#pragma unroll
                for (int q = 0; q < 4; q++)
                    CP_ASYNC16(sb + t4 * 16384 + dsts[q], gsrc[t4][q] + koff);
            CP_COMMIT();
        }

        const uint32_t B = sbase + (uint32_t)cs * 65536u;

#pragma unroll
        for (int j = 0; j < 4; j++) {
            uint32_t ah[2][4], al[2][4];
            uint32_t bh[4][4], bl[4][4];
#pragma unroll
            for (int mt = 0; mt < 2; mt++) {
                const int row = wm + mt * 16 + lrow15;
                const int unit = j * 2 + lhalf;
                const uint32_t addr = B + row * 128 + (((unit ^ (row & 7))) << 4);
                LDSM4(ah[mt], addr);
                LDSM4(al[mt], addr + 16384);
            }
#pragma unroll
            for (int g = 0; g < 4; g++) {
                const int row = wn + g * 16 + lrow15;
                const int unit = j * 2 + lhalf;
                const uint32_t addr = B + 32768 + row * 128 + (((unit ^ (row & 7))) << 4);
                LDSM4(bh[g], addr);
                LDSM4(bl[g], addr + 16384);
            }
#pragma unroll
            for (int mt = 0; mt < 2; mt++)
#pragma unroll
                for (int nt = 0; nt < 8; nt++) {
                    const int g = nt >> 1, o = nt & 1;
                    MMA_BF16(acc[mt][nt], ah[mt], bh[g][o], bh[g][o + 2]);
                    MMA_BF16(acc[mt][nt], ah[mt], bl[g][o], bl[g][o + 2]);
                    MMA_BF16(acc[mt][nt], al[mt], bh[g][o], bh[g][o + 2]);
                }
        }
        cs++; if (cs == 3) cs = 0;
    }

    const int erow = wm + (lane >> 2);
    const int ec = n0 + wn + (lane & 3) * 2;
#pragma unroll
    for (int mt = 0; mt < 2; mt++) {
        const int r0 = m0 + erow + mt * 16;
#pragma unroll
        for (int nt = 0; nt < 8; nt++) {
            const int col = ec + nt * 8;
            const float b0 = bias[col], b1 = bias[col + 1];
            float* p0 = C + (size_t)r0 * N + col;
            float* p1 = C + (size_t)(r0 + 8) * N + col;
            p0[0] = acc[mt][nt][0] + b0;
            p0[1] = acc[mt][nt][1] + b1;
            p1[0] = acc[mt][nt][2] + b0;
            p1[1] = acc[mt][nt][3] + b1;
        }
    }
}

// =====================================================================
// 2-term split-fp16 GEMM (projection), A rows compacted + scattered out.
// =====================================================================
__global__ __launch_bounds__(256, 1)
void mma_gemm_h2(const __half* __restrict__ Ahi, const __half* __restrict__ Alo,
                 const __half* __restrict__ Bh,
                 float* __restrict__ C, int N,
                 const int* __restrict__ map, const int* __restrict__ nvalidp)
{
    const int m0 = blockIdx.x * 128;
    const int n0 = blockIdx.y * 128;
    if (m0 >= *nvalidp) return;

    extern __shared__ char smc[];
    const uint32_t sbase = smem_u32(smc);

    const int tid  = threadIdx.x;
    const int wid  = tid >> 5;
    const int lane = tid & 31;
    const int wm = (wid & 3) * 32;
    const int wn = (wid >> 2) * 64;

    const __half* srcs[3] = { Ahi, Alo, Bh };
    const int rb[3] = { m0, m0, n0 };

    uint32_t dsts[4];
    const __half* gsrc[3][4];
#pragma unroll
    for (int q = 0; q < 4; q++) {
        const int i = tid + q * 256;
        const int r = i >> 3, u = i & 7;
        dsts[q] = (uint32_t)(r * 128 + ((u ^ (r & 7)) << 4));
#pragma unroll
        for (int t3 = 0; t3 < 3; t3++)
            gsrc[t3][q] = srcs[t3] + (size_t)(rb[t3] + r) * DD + u * 8;
    }

    float acc[2][8][4];
#pragma unroll
    for (int mt = 0; mt < 2; mt++)
#pragma unroll
        for (int nt = 0; nt < 8; nt++)
#pragma unroll
            for (int e = 0; e < 4; e++) acc[mt][nt][e] = 0.f;

#pragma unroll
    for (int s = 0; s < 2; s++) {
        const uint32_t sb = sbase + (uint32_t)s * 49152u;
        const int koff = s * 64;
#pragma unroll
        for (int t3 = 0; t3 < 3; t3++)
#pragma unroll
            for (int q = 0; q < 4; q++)
                CP_ASYNC16(sb + t3 * 16384 + dsts[q], gsrc[t3][q] + koff);
        CP_COMMIT();
    }

    const int lrow15 = lane & 15;
    const int lhalf  = lane >> 4;

    int cs = 0;
    for (int it = 0; it < 8; it++) {
        if (it < 7) { CP_WAIT(1); } else { CP_WAIT(0); }
        __syncthreads();

        if (it + 2 < 8) {
            int ps = cs + 2; if (ps >= 3) ps -= 3;
            const uint32_t sb = sbase + (uint32_t)ps * 49152u;
            const int koff = (it + 2) * 64;
#pragma unroll
            for (int t3 = 0; t3 < 3; t3++)
#pragma unroll
                for (int q = 0; q < 4; q++)
                    CP_ASYNC16(sb + t3 * 16384 + dsts[q], gsrc[t3][q] + koff);
            CP_COMMIT();
        }

        const uint32_t B = sbase + (uint32_t)cs * 49152u;

#pragma unroll
        for (int j = 0; j < 4; j++) {
            uint32_t ah[2][4], al[2][4];
            uint32_t bh[4][4];
#pragma unroll
            for (int mt = 0; mt < 2; mt++) {
                const int row = wm + mt * 16 + lrow15;
                const int unit = j * 2 + lhalf;
                const uint32_t addr = B + row * 128 + (((unit ^ (row & 7))) << 4);
                LDSM4(ah[mt], addr);
                LDSM4(al[mt], addr + 16384);
            }
#pragma unroll
            for (int g = 0; g < 4; g++) {
                const int row = wn + g * 16 + lrow15;
                const int unit = j * 2 + lhalf;
                const uint32_t addr = B + 32768 + row * 128 + (((unit ^ (row & 7))) << 4);
                LDSM4(bh[g], addr);
            }
#pragma unroll
            for (int mt = 0; mt < 2; mt++)
#pragma unroll
                for (int nt = 0; nt < 8; nt++) {
                    const int g = nt >> 1, o = nt & 1;
                    MMA_F16(acc[mt][nt], ah[mt], bh[g][o], bh[g][o + 2]);
                    MMA_F16(acc[mt][nt], al[mt], bh[g][o], bh[g][o + 2]);
                }
        }
        cs++; if (cs == 3) cs = 0;
    }

    const int erow = wm + (lane >> 2);
    const int ec = n0 + wn + (lane & 3) * 2;
#pragma unroll
    for (int mt = 0; mt < 2; mt++) {
        const int r0 = m0 + erow + mt * 16;
        const int r1 = r0 + 8;
        const int o0 = map[r0];
        const int o1 = map[r1];
#pragma unroll
        for (int nt = 0; nt < 8; nt++) {
            const int col = ec + nt * 8;
            if (o0 >= 0) {
                float* p0 = C + (size_t)o0 * N + col;
                p0[0] = acc[mt][nt][0];
                p0[1] = acc[mt][nt][1];
            }
            if (o1 >= 0) {
                float* p1 = C + (size_t)o1 * N + col;
                p1[0] = acc[mt][nt][2];
                p1[1] = acc[mt][nt][3];
            }
        }
    }
}

// Compact + split hs into fp16 hi/lo.
__global__ void split_compact_f16(const float* __restrict__ src,
                                  const int* __restrict__ map,
                                  __half* __restrict__ hi, __half* __restrict__ lo)
{
    const int i = blockIdx.x * 256 + threadIdx.x;
    const int j = i >> 9, k = i & 511;
    const int s = map[j];
    const float v = (s >= 0) ? src[(size_t)s * DD + k] : 0.f;
    const __half h = __float2half(v);
    hi[i] = h;
    lo[i] = __float2half(v - __half2float(h));
}

// Transpose + single fp16:  src[K=512][VV] f32  ->  h [VV][512] fp16
__global__ void transpose_f16(const float* __restrict__ src, int N,
                              __half* __restrict__ dst)
{
    __shared__ float t[32][33];
    const int tx = threadIdx.x & 31, ty = threadIdx.x >> 5;
    const int n = blockIdx.x * 32 + tx;
    const int kb = blockIdx.y * 32;
#pragma unroll
    for (int r = 0; r < 32; r += 8)
        t[ty + r][tx] = src[(size_t)(kb + ty + r) * N + n];
    __syncthreads();
#pragma unroll
    for (int r = 0; r < 32; r += 8) {
        const int nn = blockIdx.x * 32 + ty + r;
        const int kk = kb + tx;
        dst[(size_t)nn * DD + kk] = __float2half(t[tx][ty + r]);
    }
}

// =====================================================================
// Persistent LSTM: all 128 timesteps, one launch.
// Dot product uses packed f32x2 FMA (half the issue slots of scalar FFMA).
// Step sync: per-step counter, red.release arrival, relaxed-poll + final
// acquire load.
// =====================================================================
__global__ __launch_bounds__(NTHR, 1)
void lstm_persist(const float* __restrict__ pre_enc, const float* __restrict__ pre_dec,
                  const float* __restrict__ enc_Wh, const float* __restrict__ dec_Wh,
                  const int* __restrict__ len_enc, const int* __restrict__ len_dec,
                  float* __restrict__ hbuf, float* __restrict__ hs,
                  unsigned* __restrict__ scnt)
{
    extern __shared__ float smf[];
    float* whs  = smf;                    // 16*520
    float* hsm  = smf + 16 * 520;         // 32*516
    float* zbuf = hsm + 32 * 516;         // 32*17

    const int tid = threadIdx.x;
    const int cta = blockIdx.x;
    const int zc  = tid & 15;
    const int bb  = tid >> 4;
    const int b0  = bb * 2, b1 = bb * 2 + 1;

    const int gb  = tid >> 2;        // b      (gate phase, tid < 128)
    const int ghc = tid & 3;         // hc
    const int gn  = cta * 4 + ghc;   // h column

    float c_reg = 0.f;

    for (int phase = 0; phase < 2; phase++) {
        const float* Wh  = phase ? dec_Wh  : enc_Wh;
        const float* pre = phase ? pre_dec : pre_enc;
        const int*   len = phase ? len_dec : len_enc;

        for (int i = tid; i < 16 * 512; i += NTHR) {
            int z = i >> 9, k = i & 511;
            whs[z * 520 + k] =
                __ldg(&Wh[(size_t)k * G4 + (z >> 2) * 512 + cta * 4 + (z & 3)]);
        }
        const int mylen = (tid < 128) ? len[gb] : 0;
        __syncthreads();

        for (int s = 0; s < 64; s++) {
            const int sigma = phase * 64 + s;
            const float* hin  = hbuf + (sigma & 1) * (BSZ * HH);
            float*       hout = hbuf + ((sigma + 1) & 1) * (BSZ * HH);

            // Prefetch this step's pre-activations (consumed after the dot).
            float pzi = 0.f, pzj = 0.f, pzf = 0.f, pzo = 0.f;
            if (tid < 128) {
                const float* pz = pre + (size_t)s * BSZ * G4 + (size_t)gb * G4 + gn;
                pzi = __ldg(pz);
                pzj = __ldg(pz + 512);
                pzf = __ldg(pz + 1024);
                pzo = __ldg(pz + 1536);
            }

            // Stage h into smem (L2-coherent; fully unrolled for max MLP).
#pragma unroll
            for (int q = 0; q < 16; q++) {
                const int i = tid + q * NTHR;
                const int b = i >> 7, k4 = i & 127;
                float4 v = __ldcg((const float4*)&hin[b * HH + k4 * 4]);
                *(float4*)&hsm[b * 516 + k4 * 4] = v;
            }
            __syncthreads();

            // z[b][zc] = sum_k h[b][k]*whs[zc][k], packed f32x2 lanes
            uint64_t p00 = 0, p01 = 0, p10 = 0, p11 = 0;
            const float* wr  = &whs[zc * 520];
            const float* h0r = &hsm[b0 * 516];
            const float* h1r = &hsm[b1 * 516];
#pragma unroll 4
            for (int k = 0; k < 512; k += 4) {
                const ulonglong2 W = *(const ulonglong2*)&wr[k];
                const ulonglong2 A = *(const ulonglong2*)&h0r[k];
                const ulonglong2 B = *(const ulonglong2*)&h1r[k];
                fma2(p00, A.x, W.x);
                fma2(p01, A.y, W.y);
                fma2(p10, B.x, W.x);
                fma2(p11, B.y, W.y);
            }
            zbuf[b0 * 17 + zc] = pairsum(p00) + pairsum(p01);
            zbuf[b1 * 17 + zc] = pairsum(p10) + pairsum(p11);
            __syncthreads();

            if (tid < 128) {
                float zi = pzi + zbuf[gb * 17 + ghc];
                float zj = pzj + zbuf[gb * 17 + 4 + ghc];
                float zf = pzf + zbuf[gb * 17 + 8 + ghc];
                float zo = pzo + zbuf[gb * 17 + 12 + ghc];

                float fg = 1.f / (1.f + expf(-(zf + 1.0f)));   // forget bias 1.0
                float ig = 1.f / (1.f + expf(-zi));
                float og = 1.f / (1.f + expf(-zo));
                float cn = c_reg * fg + ig * tanhf(zj);
                float hn = tanhf(cn) * og;

                bool m = (s < mylen);
                float hprev = hsm[gb * 516 + gn];
                c_reg = m ? cn : c_reg;
                hout[gb * HH + gn] = m ? hn : hprev;
                if (phase)
                    hs[((size_t)gb * TY + s) * HH + gn] = m ? hn : 0.f;
            }
            __syncthreads();   // all h stores issued before arrival

            if (tid == 0) {
                unsigned* ctr = scnt + sigma;
                asm volatile("red.release.gpu.global.add.u32 [%0], 1;"
                             :: "l"(ctr) : "memory");
                unsigned v;
                do {
                    asm volatile("ld.relaxed.gpu.global.u32 %0, [%1];"
                                 : "=r"(v) : "l"(ctr) : "memory");
                } while (v < NCTA);
                asm volatile("ld.acquire.gpu.global.u32 %0, [%1];"
                             : "=r"(v) : "l"(ctr) : "memory");
            }
            __syncthreads();   // propagate tid0's acquire to the CTA
        }
    }
}

// =====================================================================
// Host launcher (graph-capturable). Launch order puts lstm_persist at
// position 6 so the fixed ncu window (-s 5 -c 1) profiles it.
// =====================================================================
extern "C" void kernel_launch(void* const* d_in, const int* in_sizes, int n_in,
                              void* d_out, int out_size)
{
    const int*   enc_ids = (const int*)d_in[0];
    const int*   dec_ids = (const int*)d_in[1];
    const int*   len_enc = (const int*)d_in[2];
    const int*   len_dec = (const int*)d_in[3];
    const float* E       = (const float*)d_in[4];
    const float* enc_W   = (const float*)d_in[5];
    const float* enc_b   = (const float*)d_in[6];
    const float* dec_W   = (const float*)d_in[7];
    const float* dec_b   = (const float*)d_in[8];
    const float* proj_W  = (const float*)d_in[9];
    float*       out     = (float*)d_out;

    float *pre_enc, *pre_dec, *hbuf, *hs;
    unsigned* scnt;
    int *map, *nvalid;
    cudaGetSymbolAddress((void**)&pre_enc, g_pre_enc);
    cudaGetSymbolAddress((void**)&pre_dec, g_pre_dec);
    cudaGetSymbolAddress((void**)&hbuf,    g_hbuf);
    cudaGetSymbolAddress((void**)&hs,      g_hs);
    cudaGetSymbolAddress((void**)&scnt,    g_scnt);
    cudaGetSymbolAddress((void**)&map,     g_map);
    cudaGetSymbolAddress((void**)&nvalid,  g_nvalid);

    __nv_bfloat16 *WeT_hi, *WeT_lo, *WdT_hi, *WdT_lo;
    __nv_bfloat16 *Ae_hi, *Ae_lo, *Ad_hi, *Ad_lo;
    __half *Bt_h, *Ah_hi, *Ah_lo;
    cudaGetSymbolAddress((void**)&WeT_hi, g_WeT_hi);
    cudaGetSymbolAddress((void**)&WeT_lo, g_WeT_lo);
    cudaGetSymbolAddress((void**)&WdT_hi, g_WdT_hi);
    cudaGetSymbolAddress((void**)&WdT_lo, g_WdT_lo);
    cudaGetSymbolAddress((void**)&Ae_hi,  g_Ae_hi);
    cudaGetSymbolAddress((void**)&Ae_lo,  g_Ae_lo);
    cudaGetSymbolAddress((void**)&Ad_hi,  g_Ad_hi);
    cudaGetSymbolAddress((void**)&Ad_lo,  g_Ad_lo);
    cudaGetSymbolAddress((void**)&Bt_h,   g_Bt_h);
    cudaGetSymbolAddress((void**)&Ah_hi,  g_Ah_hi);
    cudaGetSymbolAddress((void**)&Ah_lo,  g_Ah_lo);

    const size_t lstm_smem  = (16 * 520 + 32 * 516 + 32 * 17) * sizeof(float);
    const size_t gemm_smem  = 3 * 4 * 16384;   // 192KB (bf16 3-term)
    const size_t gemm2_smem = 3 * 3 * 16384;   // 144KB (fp16 2-term)
    static bool attr_set = false;
    if (!attr_set) {
        cudaFuncSetAttribute(lstm_persist,
                             cudaFuncAttributeMaxDynamicSharedMemorySize, (int)lstm_smem);
        cudaFuncSetAttribute(mma_gemm_pre,
                             cudaFuncAttributeMaxDynamicSharedMemorySize, (int)gemm_smem);
        cudaFuncSetAttribute(mma_gemm_h2,
                             cudaFuncAttributeMaxDynamicSharedMemorySize, (int)gemm2_smem);
        attr_set = true;
    }

    // (1) fused zero-init of h state + barrier counters
    zero_misc<<<(BSZ * HH + 255) / 256, 256>>>(hbuf, scnt);

    // (2) compact-row map from len_dec
    build_map<<<1, 128>>>(len_dec, map, nvalid);

    // (3) fused Wx transposes + splits (enc & dec)
    transpose_both<<<dim3(G4 / 32, DD / 32, 2), 256>>>(enc_W, dec_W,
                                                       WeT_hi, WeT_lo, WdT_hi, WdT_lo);

    // (4) fused embedding gathers + splits (enc & dec)
    gather_both<<<dim3((TX * BSZ * DD) / 256, 2), 256>>>(E, enc_ids, dec_ids,
                                                         Ae_hi, Ae_lo, Ad_hi, Ad_lo);

    // (5) fused pre-activation GEMMs (enc & dec)
    mma_gemm_pre<<<dim3(16, G4 / 128, 2), 256, gemm_smem>>>(
        Ae_hi, Ae_lo, WeT_hi, WeT_lo, enc_b, pre_enc,
        Ad_hi, Ad_lo, WdT_hi, WdT_lo, dec_b, pre_dec);

    // (6) full recurrence — ncu profiles this launch
    lstm_persist<<<NCTA, NTHR, lstm_smem>>>(
        pre_enc, pre_dec,
        enc_W + (size_t)DD * G4, dec_W + (size_t)DD * G4,
        len_enc, len_dec, hbuf, hs, scnt);

    // Zero output (invalid decoder rows stay zero), then projection chain.
    cudaMemsetAsync(out, 0, (size_t)out_size * sizeof(float), 0);
    transpose_f16<<<dim3(VV / 32, DD / 32), 256>>>(proj_W, VV, Bt_h);
    split_compact_f16<<<(BSZ * TY * DD) / 256, 256>>>(hs, map, Ah_hi, Ah_lo);
    mma_gemm_h2<<<dim3(16, VV / 128), 256, gemm2_smem>>>(Ah_hi, Ah_lo, Bt_h,
                                                         out, VV, map, nvalid);
}

// round 11
// speedup vs baseline: 4.5068x; 1.3137x over previous
#include <cuda_runtime.h>
#include <cuda_bf16.h>
#include <cuda_fp16.h>
#include <math.h>
#include <stdint.h>

// Problem constants
#define BSZ 32
#define TX  64
#define TY  64
#define DD  512
#define HH  512
#define G4  2048   // 4*H
#define VV  32000

#define NCTA 128   // persistent LSTM CTAs
#define NTHR 256

// ---------------- scratch (device globals; no allocation allowed) ----------------
__device__ float g_pre_enc[TX * BSZ * G4];
__device__ float g_pre_dec[TY * BSZ * G4];
__device__ float g_hbuf[2][BSZ * HH];
__device__ float g_hs[BSZ * TY * HH];
__device__ unsigned g_scnt[TX + TY];   // per-step arrival counters (zeroed each call)
__device__ int g_map[BSZ * TY];        // compact row -> original (b*64+t), -1 = pad
__device__ int g_nvalid;               // number of valid decoder rows

// bf16 3-term operands for the pre-activation GEMMs (K-major, K=512)
__device__ __nv_bfloat16 g_WeT_hi[G4 * DD], g_WeT_lo[G4 * DD];   // enc Wx^T  [4H][D]
__device__ __nv_bfloat16 g_WdT_hi[G4 * DD], g_WdT_lo[G4 * DD];   // dec Wx^T  [4H][D]
__device__ __nv_bfloat16 g_Ae_hi[TX * BSZ * DD], g_Ae_lo[TX * BSZ * DD];
__device__ __nv_bfloat16 g_Ad_hi[TY * BSZ * DD], g_Ad_lo[TY * BSZ * DD];

// fp16 2-term operands for the projection GEMM
__device__ __half g_Bt_h[VV * DD];                                // proj_W^T  [V][D], hi only
__device__ __half g_Ah_hi[BSZ * TY * DD], g_Ah_lo[BSZ * TY * DD]; // hs split fp16

// ======================= helpers =======================
__device__ __forceinline__ uint32_t smem_u32(const void* p) {
    uint32_t a;
    asm("{ .reg .u64 t; cvta.to.shared.u64 t, %1; cvt.u32.u64 %0, t; }" : "=r"(a) : "l"(p));
    return a;
}

#define LDSM4(r, addr) \
    asm volatile("ldmatrix.sync.aligned.m8n8.x4.shared.b16 {%0,%1,%2,%3}, [%4];" \
        : "=r"((r)[0]), "=r"((r)[1]), "=r"((r)[2]), "=r"((r)[3]) : "r"(addr))

#define MMA_BF16(d, a, b0, b1) \
    asm volatile("mma.sync.aligned.m16n8k16.row.col.f32.bf16.bf16.f32 " \
        "{%0,%1,%2,%3}, {%4,%5,%6,%7}, {%8,%9}, {%0,%1,%2,%3};" \
        : "+f"((d)[0]), "+f"((d)[1]), "+f"((d)[2]), "+f"((d)[3]) \
        : "r"((a)[0]), "r"((a)[1]), "r"((a)[2]), "r"((a)[3]), "r"(b0), "r"(b1))

#define MMA_F16(d, a, b0, b1) \
    asm volatile("mma.sync.aligned.m16n8k16.row.col.f32.f16.f16.f32 " \
        "{%0,%1,%2,%3}, {%4,%5,%6,%7}, {%8,%9}, {%0,%1,%2,%3};" \
        : "+f"((d)[0]), "+f"((d)[1]), "+f"((d)[2]), "+f"((d)[3]) \
        : "r"((a)[0]), "r"((a)[1]), "r"((a)[2]), "r"((a)[3]), "r"(b0), "r"(b1))

#define CP_ASYNC16(dst, src) \
    asm volatile("cp.async.cg.shared.global [%0], [%1], 16;" :: "r"(dst), "l"(src))
#define CP_COMMIT()  asm volatile("cp.async.commit_group;" ::: "memory")
#define CP_WAIT(n)   asm volatile("cp.async.wait_group %0;" :: "n"(n) : "memory")

// packed f32x2 FMA (Blackwell base ISA): d = a*b + d  elementwise on 2 floats
__device__ __forceinline__ void fma2(uint64_t& d, uint64_t a, uint64_t b) {
    asm("fma.rn.f32x2 %0, %1, %2, %0;" : "+l"(d) : "l"(a), "l"(b));
}
__device__ __forceinline__ float pairsum(uint64_t v) {
    return __uint_as_float((uint32_t)v) + __uint_as_float((uint32_t)(v >> 32));
}

// =====================================================================
// Fused zero-init: h state buffer 0 + per-step barrier counters.
// =====================================================================
__global__ void zero_misc(float* __restrict__ hbuf, unsigned* __restrict__ scnt)
{
    const int i = blockIdx.x * 256 + threadIdx.x;
    if (i < BSZ * HH) hbuf[i] = 0.f;
    if (i < TX + TY)  scnt[i] = 0u;
}

// =====================================================================
// Build compact row map from len_dec.
// =====================================================================
__global__ void build_map(const int* __restrict__ len_dec,
                          int* __restrict__ map, int* __restrict__ nvalid)
{
    __shared__ int off[BSZ];
    const int tid = threadIdx.x;
    if (tid == 0) {
        int acc = 0;
        for (int b = 0; b < BSZ; b++) {
            off[b] = acc;
            int L = len_dec[b];
            if (L < 0) L = 0;
            if (L > TY) L = TY;
            acc += L;
        }
        *nvalid = acc;
    }
    __syncthreads();
    for (int i = tid; i < BSZ * TY; i += blockDim.x) map[i] = -1;
    __syncthreads();
    for (int b = 0; b < BSZ; b++) {
        int L = len_dec[b];
        if (L > TY) L = TY;
        for (int t = tid; t < L; t += blockDim.x)
            map[off[b] + t] = b * TY + t;
    }
}

// =====================================================================
// Fused transpose + split bf16 for BOTH Wx weights (z = 0 enc, 1 dec)
// =====================================================================
__global__ void transpose_both(const float* __restrict__ srcE, const float* __restrict__ srcD,
                               __nv_bfloat16* __restrict__ hiE, __nv_bfloat16* __restrict__ loE,
                               __nv_bfloat16* __restrict__ hiD, __nv_bfloat16* __restrict__ loD)
{
    const float* src = blockIdx.z ? srcD : srcE;
    __nv_bfloat16* hi = blockIdx.z ? hiD : hiE;
    __nv_bfloat16* lo = blockIdx.z ? loD : loE;

    __shared__ float t[32][33];
    const int tx = threadIdx.x & 31, ty = threadIdx.x >> 5;
    const int n = blockIdx.x * 32 + tx;
    const int kb = blockIdx.y * 32;
#pragma unroll
    for (int r = 0; r < 32; r += 8)
        t[ty + r][tx] = src[(size_t)(kb + ty + r) * G4 + n];
    __syncthreads();
#pragma unroll
    for (int r = 0; r < 32; r += 8) {
        const int nn = blockIdx.x * 32 + ty + r;
        const int kk = kb + tx;
        const float v = t[tx][ty + r];
        const __nv_bfloat16 h = __float2bfloat16(v);
        hi[(size_t)nn * DD + kk] = h;
        lo[(size_t)nn * DD + kk] = __float2bfloat16(v - __bfloat162float(h));
    }
}

// =====================================================================
// Fused embedding gather + split bf16 for BOTH sequences (y = 0 enc, 1 dec)
// =====================================================================
__global__ void gather_both(const float* __restrict__ E,
                            const int* __restrict__ idsE, const int* __restrict__ idsD,
                            __nv_bfloat16* __restrict__ hiE, __nv_bfloat16* __restrict__ loE,
                            __nv_bfloat16* __restrict__ hiD, __nv_bfloat16* __restrict__ loD)
{
    const int* ids = blockIdx.y ? idsD : idsE;
    __nv_bfloat16* hi = blockIdx.y ? hiD : hiE;
    __nv_bfloat16* lo = blockIdx.y ? loD : loE;
    const int idxT = blockIdx.y ? TY : TX;

    const int i = blockIdx.x * 256 + threadIdx.x;
    const int row = i >> 9, k = i & 511;
    const int b = row & 31, t = row >> 5;
    const float v = E[(size_t)ids[b * idxT + t] * DD + k];
    const __nv_bfloat16 h = __float2bfloat16(v);
    hi[i] = h;
    lo[i] = __float2bfloat16(v - __bfloat162float(h));
}

// =====================================================================
// Fused 3-term split-bf16 GEMM for BOTH pre-activations (z = 0 enc, 1 dec)
// =====================================================================
__global__ __launch_bounds__(256, 1)
void mma_gemm_pre(const __nv_bfloat16* __restrict__ AhiE, const __nv_bfloat16* __restrict__ AloE,
                  const __nv_bfloat16* __restrict__ BhiE, const __nv_bfloat16* __restrict__ BloE,
                  const float* __restrict__ biasE, float* __restrict__ CE,
                  const __nv_bfloat16* __restrict__ AhiD, const __nv_bfloat16* __restrict__ AloD,
                  const __nv_bfloat16* __restrict__ BhiD, const __nv_bfloat16* __restrict__ BloD,
                  const float* __restrict__ biasD, float* __restrict__ CD)
{
    const __nv_bfloat16* Ahi = blockIdx.z ? AhiD : AhiE;
    const __nv_bfloat16* Alo = blockIdx.z ? AloD : AloE;
    const __nv_bfloat16* Bhi = blockIdx.z ? BhiD : BhiE;
    const __nv_bfloat16* Blo = blockIdx.z ? BloD : BloE;
    const float* bias = blockIdx.z ? biasD : biasE;
    float* C = blockIdx.z ? CD : CE;
    const int N = G4;

    extern __shared__ char smc[];
    const uint32_t sbase = smem_u32(smc);

    const int tid  = threadIdx.x;
    const int wid  = tid >> 5;
    const int lane = tid & 31;
    const int m0 = blockIdx.x * 128;
    const int n0 = blockIdx.y * 128;
    const int wm = (wid & 3) * 32;
    const int wn = (wid >> 2) * 64;

    const __nv_bfloat16* srcs[4] = { Ahi, Alo, Bhi, Blo };
    const int rb[4] = { m0, m0, n0, n0 };

    uint32_t dsts[4];
    const __nv_bfloat16* gsrc[4][4];
#pragma unroll
    for (int q = 0; q < 4; q++) {
        const int i = tid + q * 256;
        const int r = i >> 3, u = i & 7;
        dsts[q] = (uint32_t)(r * 128 + ((u ^ (r & 7)) << 4));
#pragma unroll
        for (int t4 = 0; t4 < 4; t4++)
            gsrc[t4][q] = srcs[t4] + (size_t)(rb[t4] + r) * DD + u * 8;
    }

    float acc[2][8][4];
#pragma unroll
    for (int mt = 0; mt < 2; mt++)
#pragma unroll
        for (int nt = 0; nt < 8; nt++)
#pragma unroll
            for (int e = 0; e < 4; e++) acc[mt][nt][e] = 0.f;

#pragma unroll
    for (int s = 0; s < 2; s++) {
        const uint32_t sb = sbase + (uint32_t)s * 65536u;
        const int koff = s * 64;
#pragma unroll
        for (int t4 = 0; t4 < 4; t4++)
#pragma unroll
            for (int q = 0; q < 4; q++)
                CP_ASYNC16(sb + t4 * 16384 + dsts[q], gsrc[t4][q] + koff);
        CP_COMMIT();
    }

    const int lrow15 = lane & 15;
    const int lhalf  = lane >> 4;

    int cs = 0;
    for (int it = 0; it < 8; it++) {
        if (it < 7) { CP_WAIT(1); } else { CP_WAIT(0); }
        __syncthreads();

        if (it + 2 < 8) {
            int ps = cs + 2; if (ps >= 3) ps -= 3;
            const uint32_t sb = sbase + (uint32_t)ps * 65536u;
            const int koff = (it + 2) * 64;
#pragma unroll
            for (int t4 = 0; t4 < 4; t4++)
#pragma unroll
                for (int q = 0; q < 4; q++)
                    CP_ASYNC16(sb + t4 * 16384 + dsts[q], gsrc[t4][q] + koff);
            CP_COMMIT();
        }

        const uint32_t B = sbase + (uint32_t)cs * 65536u;

#pragma unroll
        for (int j = 0; j < 4; j++) {
            uint32_t ah[2][4], al[2][4];
            uint32_t bh[4][4], bl[4][4];
#pragma unroll
            for (int mt = 0; mt < 2; mt++) {
                const int row = wm + mt * 16 + lrow15;
                const int unit = j * 2 + lhalf;
                const uint32_t addr = B + row * 128 + (((unit ^ (row & 7))) << 4);
                LDSM4(ah[mt], addr);
                LDSM4(al[mt], addr + 16384);
            }
#pragma unroll
            for (int g = 0; g < 4; g++) {
                const int row = wn + g * 16 + lrow15;
                const int unit = j * 2 + lhalf;
                const uint32_t addr = B + 32768 + row * 128 + (((unit ^ (row & 7))) << 4);
                LDSM4(bh[g], addr);
                LDSM4(bl[g], addr + 16384);
            }
#pragma unroll
            for (int mt = 0; mt < 2; mt++)
#pragma unroll
                for (int nt = 0; nt < 8; nt++) {
                    const int g = nt >> 1, o = nt & 1;
                    MMA_BF16(acc[mt][nt], ah[mt], bh[g][o], bh[g][o + 2]);
                    MMA_BF16(acc[mt][nt], ah[mt], bl[g][o], bl[g][o + 2]);
                    MMA_BF16(acc[mt][nt], al[mt], bh[g][o], bh[g][o + 2]);
                }
        }
        cs++; if (cs == 3) cs = 0;
    }

    const int erow = wm + (lane >> 2);
    const int ec = n0 + wn + (lane & 3) * 2;
#pragma unroll
    for (int mt = 0; mt < 2; mt++) {
        const int r0 = m0 + erow + mt * 16;
#pragma unroll
        for (int nt = 0; nt < 8; nt++) {
            const int col = ec + nt * 8;
            const float b0 = bias[col], b1 = bias[col + 1];
            float* p0 = C + (size_t)r0 * N + col;
            float* p1 = C + (size_t)(r0 + 8) * N + col;
            p0[0] = acc[mt][nt][0] + b0;
            p0[1] = acc[mt][nt][1] + b1;
            p1[0] = acc[mt][nt][2] + b0;
            p1[1] = acc[mt][nt][3] + b1;
        }
    }
}

// =====================================================================
// 2-term split-fp16 GEMM (projection), A rows compacted + scattered out.
// =====================================================================
__global__ __launch_bounds__(256, 1)
void mma_gemm_h2(const __half* __restrict__ Ahi, const __half* __restrict__ Alo,
                 const __half* __restrict__ Bh,
                 float* __restrict__ C, int N,
                 const int* __restrict__ map, const int* __restrict__ nvalidp)
{
    const int m0 = blockIdx.x * 128;
    const int n0 = blockIdx.y * 128;
    if (m0 >= *nvalidp) return;

    extern __shared__ char smc[];
    const uint32_t sbase = smem_u32(smc);

    const int tid  = threadIdx.x;
    const int wid  = tid >> 5;
    const int lane = tid & 31;
    const int wm = (wid & 3) * 32;
    const int wn = (wid >> 2) * 64;

    const __half* srcs[3] = { Ahi, Alo, Bh };
    const int rb[3] = { m0, m0, n0 };

    uint32_t dsts[4];
    const __half* gsrc[3][4];
#pragma unroll
    for (int q = 0; q < 4; q++) {
        const int i = tid + q * 256;
        const int r = i >> 3, u = i & 7;
        dsts[q] = (uint32_t)(r * 128 + ((u ^ (r & 7)) << 4));
#pragma unroll
        for (int t3 = 0; t3 < 3; t3++)
            gsrc[t3][q] = srcs[t3] + (size_t)(rb[t3] + r) * DD + u * 8;
    }

    float acc[2][8][4];
#pragma unroll
    for (int mt = 0; mt < 2; mt++)
#pragma unroll
        for (int nt = 0; nt < 8; nt++)
#pragma unroll
            for (int e = 0; e < 4; e++) acc[mt][nt][e] = 0.f;

#pragma unroll
    for (int s = 0; s < 2; s++) {
        const uint32_t sb = sbase + (uint32_t)s * 49152u;
        const int koff = s * 64;
#pragma unroll
        for (int t3 = 0; t3 < 3; t3++)
#pragma unroll
            for (int q = 0; q < 4; q++)
                CP_ASYNC16(sb + t3 * 16384 + dsts[q], gsrc[t3][q] + koff);
        CP_COMMIT();
    }

    const int lrow15 = lane & 15;
    const int lhalf  = lane >> 4;

    int cs = 0;
    for (int it = 0; it < 8; it++) {
        if (it < 7) { CP_WAIT(1); } else { CP_WAIT(0); }
        __syncthreads();

        if (it + 2 < 8) {
            int ps = cs + 2; if (ps >= 3) ps -= 3;
            const uint32_t sb = sbase + (uint32_t)ps * 49152u;
            const int koff = (it + 2) * 64;
#pragma unroll
            for (int t3 = 0; t3 < 3; t3++)
#pragma unroll
                for (int q = 0; q < 4; q++)
                    CP_ASYNC16(sb + t3 * 16384 + dsts[q], gsrc[t3][q] + koff);
            CP_COMMIT();
        }

        const uint32_t B = sbase + (uint32_t)cs * 49152u;

#pragma unroll
        for (int j = 0; j < 4; j++) {
            uint32_t ah[2][4], al[2][4];
            uint32_t bh[4][4];
#pragma unroll
            for (int mt = 0; mt < 2; mt++) {
                const int row = wm + mt * 16 + lrow15;
                const int unit = j * 2 + lhalf;
                const uint32_t addr = B + row * 128 + (((unit ^ (row & 7))) << 4);
                LDSM4(ah[mt], addr);
                LDSM4(al[mt], addr + 16384);
            }
#pragma unroll
            for (int g = 0; g < 4; g++) {
                const int row = wn + g * 16 + lrow15;
                const int unit = j * 2 + lhalf;
                const uint32_t addr = B + 32768 + row * 128 + (((unit ^ (row & 7))) << 4);
                LDSM4(bh[g], addr);
            }
#pragma unroll
            for (int mt = 0; mt < 2; mt++)
#pragma unroll
                for (int nt = 0; nt < 8; nt++) {
                    const int g = nt >> 1, o = nt & 1;
                    MMA_F16(acc[mt][nt], ah[mt], bh[g][o], bh[g][o + 2]);
                    MMA_F16(acc[mt][nt], al[mt], bh[g][o], bh[g][o + 2]);
                }
        }
        cs++; if (cs == 3) cs = 0;
    }

    const int erow = wm + (lane >> 2);
    const int ec = n0 + wn + (lane & 3) * 2;
#pragma unroll
    for (int mt = 0; mt < 2; mt++) {
        const int r0 = m0 + erow + mt * 16;
        const int r1 = r0 + 8;
        const int o0 = map[r0];
        const int o1 = map[r1];
#pragma unroll
        for (int nt = 0; nt < 8; nt++) {
            const int col = ec + nt * 8;
            if (o0 >= 0) {
                float* p0 = C + (size_t)o0 * N + col;
                p0[0] = acc[mt][nt][0];
                p0[1] = acc[mt][nt][1];
            }
            if (o1 >= 0) {
                float* p1 = C + (size_t)o1 * N + col;
                p1[0] = acc[mt][nt][2];
                p1[1] = acc[mt][nt][3];
            }
        }
    }
}

// Compact + split hs into fp16 hi/lo.
__global__ void split_compact_f16(const float* __restrict__ src,
                                  const int* __restrict__ map,
                                  __half* __restrict__ hi, __half* __restrict__ lo)
{
    const int i = blockIdx.x * 256 + threadIdx.x;
    const int j = i >> 9, k = i & 511;
    const int s = map[j];
    const float v = (s >= 0) ? src[(size_t)s * DD + k] : 0.f;
    const __half h = __float2half(v);
    hi[i] = h;
    lo[i] = __float2half(v - __half2float(h));
}

// Transpose + single fp16:  src[K=512][VV] f32  ->  h [VV][512] fp16
__global__ void transpose_f16(const float* __restrict__ src, int N,
                              __half* __restrict__ dst)
{
    __shared__ float t[32][33];
    const int tx = threadIdx.x & 31, ty = threadIdx.x >> 5;
    const int n = blockIdx.x * 32 + tx;
    const int kb = blockIdx.y * 32;
#pragma unroll
    for (int r = 0; r < 32; r += 8)
        t[ty + r][tx] = src[(size_t)(kb + ty + r) * N + n];
    __syncthreads();
#pragma unroll
    for (int r = 0; r < 32; r += 8) {
        const int nn = blockIdx.x * 32 + ty + r;
        const int kk = kb + tx;
        dst[(size_t)nn * DD + kk] = __float2half(t[tx][ty + r]);
    }
}

// =====================================================================
// Persistent LSTM: all 128 timesteps, one launch.
// Dot: 8 warps = 2(k-half) x 2(b-half) x 2(zc-half); each lane owns a
// 2b x 2zc register tile -> 4 conflict-free LDS.128 + 8 FMA2 per k4.
// Crossbar traffic/step drops ~3.5x vs previous layout.
// =====================================================================
__global__ __launch_bounds__(NTHR, 1)
void lstm_persist(const float* __restrict__ pre_enc, const float* __restrict__ pre_dec,
                  const float* __restrict__ enc_Wh, const float* __restrict__ dec_Wh,
                  const int* __restrict__ len_enc, const int* __restrict__ len_dec,
                  float* __restrict__ hbuf, float* __restrict__ hs,
                  unsigned* __restrict__ scnt)
{
    extern __shared__ float smf[];
    float* whs  = smf;                    // 16*516 (stride 516: rows spread banks)
    float* hsm  = smf + 16 * 516;         // 32*516
    float* zbuf = hsm + 32 * 516;         // 2 * 32*17 (two k-half partials)

    const int tid = threadIdx.x;
    const int cta = blockIdx.x;
    const int wid = tid >> 5;
    const int lane = tid & 31;

    // dot-phase decomposition
    const int wk = wid >> 2;              // k half: k in [wk*256, wk*256+256)
    const int wq = wid & 3;
    const int base_b = (wq & 1) * 16;
    const int base_z = (wq >> 1) * 8;
    const int lb = lane & 7;
    const int lz = lane >> 3;             // 0..3
    const int rb0 = base_b + lb,     rb1 = base_b + 8 + lb;
    const int rz0 = base_z + lz,     rz1 = base_z + 4 + lz;
    const int kof = wk * 256;

    // gate-phase constants (tid < 128)
    const int gb  = tid >> 2;        // b
    const int ghc = tid & 3;         // hc
    const int gn  = cta * 4 + ghc;   // h column

    float c_reg = 0.f;

    for (int phase = 0; phase < 2; phase++) {
        const float* Wh  = phase ? dec_Wh  : enc_Wh;
        const float* pre = phase ? pre_dec : pre_enc;
        const int*   len = phase ? len_dec : len_enc;

        // Load Wh slice transposed: whs[z][k], z = g*4+hc for this CTA.
        for (int i = tid; i < 16 * 512; i += NTHR) {
            int z = i >> 9, k = i & 511;
            whs[z * 516 + k] =
                __ldg(&Wh[(size_t)k * G4 + (z >> 2) * 512 + cta * 4 + (z & 3)]);
        }
        const int mylen = (tid < 128) ? len[gb] : 0;
        __syncthreads();

        for (int s = 0; s < 64; s++) {
            const int sigma = phase * 64 + s;
            const float* hin  = hbuf + (sigma & 1) * (BSZ * HH);
            float*       hout = hbuf + ((sigma + 1) & 1) * (BSZ * HH);

            // Prefetch this step's pre-activations (consumed after the dot).
            float pzi = 0.f, pzj = 0.f, pzf = 0.f, pzo = 0.f;
            if (tid < 128) {
                const float* pz = pre + (size_t)s * BSZ * G4 + (size_t)gb * G4 + gn;
                pzi = __ldg(pz);
                pzj = __ldg(pz + 512);
                pzf = __ldg(pz + 1024);
                pzo = __ldg(pz + 1536);
            }

            // Stage h into smem (L2-coherent; fully unrolled for max MLP).
#pragma unroll
            for (int q = 0; q < 16; q++) {
                const int i = tid + q * NTHR;
                const int b = i >> 7, k4 = i & 127;
                float4 v = __ldcg((const float4*)&hin[b * HH + k4 * 4]);
                *(float4*)&hsm[b * 516 + k4 * 4] = v;
            }
            __syncthreads();

            // 2b x 2zc register tile over this warp's k-half.
            const float* A0 = &hsm[rb0 * 516 + kof];
            const float* A1 = &hsm[rb1 * 516 + kof];
            const float* W0 = &whs[rz0 * 516 + kof];
            const float* W1 = &whs[rz1 * 516 + kof];
            uint64_t a00 = 0, a01 = 0, a10 = 0, a11 = 0;
#pragma unroll 4
            for (int k = 0; k < 256; k += 4) {
                const ulonglong2 va0 = *(const ulonglong2*)(A0 + k);
                const ulonglong2 va1 = *(const ulonglong2*)(A1 + k);
                const ulonglong2 vw0 = *(const ulonglong2*)(W0 + k);
                const ulonglong2 vw1 = *(const ulonglong2*)(W1 + k);
                fma2(a00, va0.x, vw0.x); fma2(a00, va0.y, vw0.y);
                fma2(a01, va0.x, vw1.x); fma2(a01, va0.y, vw1.y);
                fma2(a10, va1.x, vw0.x); fma2(a10, va1.y, vw0.y);
                fma2(a11, va1.x, vw1.x); fma2(a11, va1.y, vw1.y);
            }
            float* zb = zbuf + wk * 544;
            zb[rb0 * 17 + rz0] = pairsum(a00);
            zb[rb0 * 17 + rz1] = pairsum(a01);
            zb[rb1 * 17 + rz0] = pairsum(a10);
            zb[rb1 * 17 + rz1] = pairsum(a11);
            __syncthreads();

            if (tid < 128) {
                const int zi0 = gb * 17 + ghc;
                float zi = pzi + zbuf[zi0]      + zbuf[544 + zi0];
                float zj = pzj + zbuf[zi0 + 4]  + zbuf[544 + zi0 + 4];
                float zf = pzf + zbuf[zi0 + 8]  + zbuf[544 + zi0 + 8];
                float zo = pzo + zbuf[zi0 + 12] + zbuf[544 + zi0 + 12];

                float fg = 1.f / (1.f + expf(-(zf + 1.0f)));   // forget bias 1.0
                float ig = 1.f / (1.f + expf(-zi));
                float og = 1.f / (1.f + expf(-zo));
                float cn = c_reg * fg + ig * tanhf(zj);
                float hn = tanhf(cn) * og;

                bool m = (s < mylen);
                float hprev = hsm[gb * 516 + gn];
                c_reg = m ? cn : c_reg;
                hout[gb * HH + gn] = m ? hn : hprev;
                if (phase)
                    hs[((size_t)gb * TY + s) * HH + gn] = m ? hn : 0.f;
            }
            __syncthreads();   // all h stores issued before arrival

            if (tid == 0) {
                unsigned* ctr = scnt + sigma;
                asm volatile("red.release.gpu.global.add.u32 [%0], 1;"
                             :: "l"(ctr) : "memory");
                unsigned v;
                do {
                    asm volatile("ld.relaxed.gpu.global.u32 %0, [%1];"
                                 : "=r"(v) : "l"(ctr) : "memory");
                } while (v < NCTA);
                asm volatile("ld.acquire.gpu.global.u32 %0, [%1];"
                             : "=r"(v) : "l"(ctr) : "memory");
            }
            __syncthreads();   // propagate tid0's acquire to the CTA
        }
    }
}

// =====================================================================
// Host launcher (graph-capturable)
// =====================================================================
extern "C" void kernel_launch(void* const* d_in, const int* in_sizes, int n_in,
                              void* d_out, int out_size)
{
    const int*   enc_ids = (const int*)d_in[0];
    const int*   dec_ids = (const int*)d_in[1];
    const int*   len_enc = (const int*)d_in[2];
    const int*   len_dec = (const int*)d_in[3];
    const float* E       = (const float*)d_in[4];
    const float* enc_W   = (const float*)d_in[5];
    const float* enc_b   = (const float*)d_in[6];
    const float* dec_W   = (const float*)d_in[7];
    const float* dec_b   = (const float*)d_in[8];
    const float* proj_W  = (const float*)d_in[9];
    float*       out     = (float*)d_out;

    float *pre_enc, *pre_dec, *hbuf, *hs;
    unsigned* scnt;
    int *map, *nvalid;
    cudaGetSymbolAddress((void**)&pre_enc, g_pre_enc);
    cudaGetSymbolAddress((void**)&pre_dec, g_pre_dec);
    cudaGetSymbolAddress((void**)&hbuf,    g_hbuf);
    cudaGetSymbolAddress((void**)&hs,      g_hs);
    cudaGetSymbolAddress((void**)&scnt,    g_scnt);
    cudaGetSymbolAddress((void**)&map,     g_map);
    cudaGetSymbolAddress((void**)&nvalid,  g_nvalid);

    __nv_bfloat16 *WeT_hi, *WeT_lo, *WdT_hi, *WdT_lo;
    __nv_bfloat16 *Ae_hi, *Ae_lo, *Ad_hi, *Ad_lo;
    __half *Bt_h, *Ah_hi, *Ah_lo;
    cudaGetSymbolAddress((void**)&WeT_hi, g_WeT_hi);
    cudaGetSymbolAddress((void**)&WeT_lo, g_WeT_lo);
    cudaGetSymbolAddress((void**)&WdT_hi, g_WdT_hi);
    cudaGetSymbolAddress((void**)&WdT_lo, g_WdT_lo);
    cudaGetSymbolAddress((void**)&Ae_hi,  g_Ae_hi);
    cudaGetSymbolAddress((void**)&Ae_lo,  g_Ae_lo);
    cudaGetSymbolAddress((void**)&Ad_hi,  g_Ad_hi);
    cudaGetSymbolAddress((void**)&Ad_lo,  g_Ad_lo);
    cudaGetSymbolAddress((void**)&Bt_h,   g_Bt_h);
    cudaGetSymbolAddress((void**)&Ah_hi,  g_Ah_hi);
    cudaGetSymbolAddress((void**)&Ah_lo,  g_Ah_lo);

    const size_t lstm_smem  = (16 * 516 + 32 * 516 + 2 * 544) * sizeof(float);
    const size_t gemm_smem  = 3 * 4 * 16384;   // 192KB (bf16 3-term)
    const size_t gemm2_smem = 3 * 3 * 16384;   // 144KB (fp16 2-term)
    static bool attr_set = false;
    if (!attr_set) {
        cudaFuncSetAttribute(lstm_persist,
                             cudaFuncAttributeMaxDynamicSharedMemorySize, (int)lstm_smem);
        cudaFuncSetAttribute(mma_gemm_pre,
                             cudaFuncAttributeMaxDynamicSharedMemorySize, (int)gemm_smem);
        cudaFuncSetAttribute(mma_gemm_h2,
                             cudaFuncAttributeMaxDynamicSharedMemorySize, (int)gemm2_smem);
        attr_set = true;
    }

    // (1) fused zero-init of h state + barrier counters
    zero_misc<<<(BSZ * HH + 255) / 256, 256>>>(hbuf, scnt);

    // (2) compact-row map from len_dec
    build_map<<<1, 128>>>(len_dec, map, nvalid);

    // (3) fused Wx transposes + splits (enc & dec)
    transpose_both<<<dim3(G4 / 32, DD / 32, 2), 256>>>(enc_W, dec_W,
                                                       WeT_hi, WeT_lo, WdT_hi, WdT_lo);

    // (4) fused embedding gathers + splits (enc & dec)
    gather_both<<<dim3((TX * BSZ * DD) / 256, 2), 256>>>(E, enc_ids, dec_ids,
                                                         Ae_hi, Ae_lo, Ad_hi, Ad_lo);

    // (5) fused pre-activation GEMMs (enc & dec)
    mma_gemm_pre<<<dim3(16, G4 / 128, 2), 256, gemm_smem>>>(
        Ae_hi, Ae_lo, WeT_hi, WeT_lo, enc_b, pre_enc,
        Ad_hi, Ad_lo, WdT_hi, WdT_lo, dec_b, pre_dec);

    // (6) full recurrence
    lstm_persist<<<NCTA, NTHR, lstm_smem>>>(
        pre_enc, pre_dec,
        enc_W + (size_t)DD * G4, dec_W + (size_t)DD * G4,
        len_enc, len_dec, hbuf, hs, scnt);

    // Zero output (invalid decoder rows stay zero), then projection chain.
    cudaMemsetAsync(out, 0, (size_t)out_size * sizeof(float), 0);
    transpose_f16<<<dim3(VV / 32, DD / 32), 256>>>(proj_W, VV, Bt_h);
    split_compact_f16<<<(BSZ * TY * DD) / 256, 256>>>(hs, map, Ah_hi, Ah_lo);
    mma_gemm_h2<<<dim3(16, VV / 128), 256, gemm2_smem>>>(Ah_hi, Ah_lo, Bt_h,
                                                         out, VV, map, nvalid);
}